// round 12
// baseline (speedup 1.0000x reference)
#include <cuda_runtime.h>
#include <cuda_bf16.h>
#include <cstdint>

#define T_  64
#define B_  32
#define E_  512
#define H_  8
#define F_  2048
#define TB_ (T_*B_)        // 2048
#define ROWS_ (T_*T_*B_)   // 131072
#define NCHUNK 4
#define CROWS (ROWS_/NCHUNK)   // 32768 rows per chunk

// ---------------- scratch ----------------------------------------------------
__device__ float g_qkv[TB_ * 3 * E_];
__device__ float g_w[TB_ * H_ * T_];
__device__ float g_attn[TB_ * E_];
__device__ float g_ao[TB_ * E_];
__device__ float g_h[TB_ * E_];
__device__ float g_f1[TB_ * F_];
__device__ float g_f2[TB_ * E_];
__device__ __nv_bfloat16 g_arel[(size_t)ROWS_ * E_];   // relation in bf16 (134MB)
__device__ __nv_bfloat16 g_bw[H_ * E_ * 128];          // [h][k][2d interleaved ra/rb]

// ---------------- helpers ------------------------------------------------------
__device__ __forceinline__ uint32_t smem_u32(const void* p) {
    return (uint32_t)__cvta_generic_to_shared(p);
}
__device__ __forceinline__ void ldsm_x4(uint32_t& r0, uint32_t& r1, uint32_t& r2, uint32_t& r3, uint32_t a) {
    asm volatile("ldmatrix.sync.aligned.m8n8.x4.shared.b16 {%0,%1,%2,%3},[%4];"
                 : "=r"(r0), "=r"(r1), "=r"(r2), "=r"(r3) : "r"(a));
}
__device__ __forceinline__ void ldsm_x4_t(uint32_t& r0, uint32_t& r1, uint32_t& r2, uint32_t& r3, uint32_t a) {
    asm volatile("ldmatrix.sync.aligned.m8n8.x4.trans.shared.b16 {%0,%1,%2,%3},[%4];"
                 : "=r"(r0), "=r"(r1), "=r"(r2), "=r"(r3) : "r"(a));
}
__device__ __forceinline__ void mma16816(float* c, const uint32_t* a, const uint32_t* b) {
    asm volatile("mma.sync.aligned.m16n8k16.row.col.f32.bf16.bf16.f32 "
                 "{%0,%1,%2,%3},{%4,%5,%6,%7},{%8,%9},{%0,%1,%2,%3};"
                 : "+f"(c[0]), "+f"(c[1]), "+f"(c[2]), "+f"(c[3])
                 : "r"(a[0]), "r"(a[1]), "r"(a[2]), "r"(a[3]), "r"(b[0]), "r"(b[1]));
}
__device__ __forceinline__ void mma_tf32(float* c, const float* a, const float* b) {
    asm volatile("mma.sync.aligned.m16n8k8.row.col.f32.tf32.tf32.f32 "
                 "{%0,%1,%2,%3},{%4,%5,%6,%7},{%8,%9},{%0,%1,%2,%3};"
                 : "+f"(c[0]), "+f"(c[1]), "+f"(c[2]), "+f"(c[3])
                 : "r"(__float_as_uint(a[0])), "r"(__float_as_uint(a[1])),
                   "r"(__float_as_uint(a[2])), "r"(__float_as_uint(a[3])),
                   "r"(__float_as_uint(b[0])), "r"(__float_as_uint(b[1])));
}
__device__ __forceinline__ uint32_t f2bf2(float x, float y) {
    __nv_bfloat162 t = __floats2bfloat162_rn(x, y);
    return *reinterpret_cast<uint32_t*>(&t);
}
#define CP_ASYNC16(saddr, gptr) \
    asm volatile("cp.async.cg.shared.global [%0], [%1], 16;" :: "r"(saddr), "l"(gptr) : "memory")
#define CP_COMMIT() asm volatile("cp.async.commit_group;" ::: "memory")
#define CP_WAIT1()  asm volatile("cp.async.wait_group 1;" ::: "memory")
#define CP_WAIT0()  asm volatile("cp.async.wait_group 0;" ::: "memory")

// ---------------- prepass: relation fp32 -> bf16 (chunked) --------------------
__global__ __launch_bounds__(256) void cvt_rel(const float* __restrict__ rel,
                                               __nv_bfloat16* __restrict__ dst)
{
    size_t i = ((size_t)blockIdx.x * 256 + threadIdx.x) * 8;
    float4 a = *(const float4*)(rel + i);
    float4 b = *(const float4*)(rel + i + 4);
    uint4 v = make_uint4(f2bf2(a.x, a.y), f2bf2(a.z, a.w),
                         f2bf2(b.x, b.y), f2bf2(b.z, b.w));
    *(uint4*)((char*)dst + i * 2) = v;
}

// ---------------- prepass: interleaved bf16 weight tiles [h][k][128] ----------
__global__ __launch_bounds__(256) void build_bw(const float* __restrict__ relw)
{
    int idx = blockIdx.x * 256 + threadIdx.x;    // 262144
    int d = idx & 63;
    int k = (idx >> 6) & 511;
    int h = idx >> 15;
    g_bw[((size_t)h*E_ + k) * 128 + 2*d    ] = __float2bfloat16(relw[(size_t)k*(2*E_) + h*64 + d]);
    g_bw[((size_t)h*E_ + k) * 128 + 2*d + 1] = __float2bfloat16(relw[(size_t)k*(2*E_) + E_ + h*64 + d]);
}

// ---------------- fused relation GEMM (bf16 HMMA, 3-stage, 2 CTAs/SM) ---------
#define RSA_STRIDE 16384
#define RSB_BASE   49152
#define RSB_STRIDE 16384
#define RELW_SMEM  98304
__global__ void __launch_bounds__(256, 2) relw_mma(const float* __restrict__ relb,
                                                   int row_base)
{
    extern __shared__ char smem[];
    const uint32_t AsBase = smem_u32(smem);
    const uint32_t BsBase = AsBase + RSB_BASE;
    float* red = (float*)smem;

    const int h   = blockIdx.x;
    const int n0  = row_base + blockIdx.y * 128;
    const int tid = threadIdx.x;
    const int lane = tid & 31, warp = tid >> 5;
    const int warp_m = warp >> 1, warp_n = warp & 1;

    float acc[2][8][4];
    #pragma unroll
    for (int i = 0; i < 2; i++)
        #pragma unroll
        for (int j = 0; j < 8; j++)
            #pragma unroll
            for (int k = 0; k < 4; k++) acc[i][j][k] = 0.f;

    const __nv_bfloat16* Ag = g_arel + (size_t)n0 * E_;
    const __nv_bfloat16* Bg = g_bw + (size_t)h * E_ * 128;

    auto load_stage = [&](int s, int buf) {
        uint32_t Ab = AsBase + buf * RSA_STRIDE;
        #pragma unroll
        for (int c = 0; c < 4; c++) {
            int idx = c * 256 + tid;
            int row = idx >> 3, cg = idx & 7;
            CP_ASYNC16(Ab + row*128 + (((cg ^ (row & 7)) << 4)),
                       Ag + (size_t)row * E_ + s*64 + cg*8);
        }
        uint32_t Bb = BsBase + buf * RSB_STRIDE;
        #pragma unroll
        for (int c = 0; c < 4; c++) {
            int idx = c * 256 + tid;
            int kr = idx >> 4, ng = idx & 15;
            CP_ASYNC16(Bb + kr*256 + (((ng ^ (kr & 7)) << 4)),
                       Bg + (size_t)(s*64 + kr) * 128 + ng*8);
        }
        CP_COMMIT();
    };

    load_stage(0, 0);
    load_stage(1, 1);

    const int a_r  = warp_m*32 + (lane & 15);
    const int a_kc = (lane >> 4) << 3;
    const int b_kr = lane & 15;
    const int b_nc = warp_n*64 + ((lane >> 4) << 3);

    #pragma unroll
    for (int s = 0; s < 8; s++) {
        if (s < 7) CP_WAIT1(); else CP_WAIT0();
        __syncthreads();
        if (s < 6) load_stage(s + 2, (s + 2) % 3);

        const uint32_t Ab = AsBase + (s % 3) * RSA_STRIDE;
        const uint32_t Bb = BsBase + (s % 3) * RSB_STRIDE;

        #pragma unroll
        for (int ks = 0; ks < 4; ks++) {
            uint32_t a[2][4];
            #pragma unroll
            for (int mi = 0; mi < 2; mi++) {
                int r  = a_r + mi*16;
                int kc = a_kc + ks*16;
                ldsm_x4(a[mi][0], a[mi][1], a[mi][2], a[mi][3],
                        Ab + r*128 + ((((kc >> 3) ^ (r & 7)) << 4)));
            }
            uint32_t b[8][2];
            #pragma unroll
            for (int g = 0; g < 4; g++) {
                int krow = b_kr + ks*16;
                int ncol = b_nc + g*16;
                ldsm_x4_t(b[2*g][0], b[2*g][1], b[2*g+1][0], b[2*g+1][1],
                          Bb + krow*256 + ((((ncol >> 3) ^ (krow & 7)) << 4)));
            }
            #pragma unroll
            for (int mi = 0; mi < 2; mi++)
                #pragma unroll
                for (int nf = 0; nf < 8; nf++)
                    mma16816(acc[mi][nf], a[mi], b[nf]);
        }
    }

    // ---- fused epilogue --------------------------------------------------------
    const int tig = lane & 3, grp = lane >> 2;
    float part[2][2] = {{0.f, 0.f}, {0.f, 0.f}};
    #pragma unroll
    for (int nf = 0; nf < 8; nf++) {
        int d = warp_n*32 + nf*4 + tig;
        float bra = relb[h*64 + d];
        float brb = relb[E_ + h*64 + d];
        #pragma unroll
        for (int mi = 0; mi < 2; mi++)
            #pragma unroll
            for (int hf = 0; hf < 2; hf++) {
                int r  = warp_m*32 + mi*16 + grp + hf*8;
                int n  = n0 + r;
                int b  = n & 31;
                int ji = n >> 5;
                int ii = ji & 63, jj = ji >> 6;
                float q = g_qkv[(size_t)(ii*B_ + b) * (3*E_) + h*64 + d];
                float k = g_qkv[(size_t)(jj*B_ + b) * (3*E_) + E_ + h*64 + d];
                part[mi][hf] += (acc[mi][nf][hf*2+0] + bra + q) * (acc[mi][nf][hf*2+1] + brb + k);
            }
    }
    #pragma unroll
    for (int mi = 0; mi < 2; mi++)
        #pragma unroll
        for (int hf = 0; hf < 2; hf++) {
            float v = part[mi][hf];
            v += __shfl_xor_sync(~0u, v, 1);
            v += __shfl_xor_sync(~0u, v, 2);
            part[mi][hf] = v;
        }
    __syncthreads();
    if (tig == 0) {
        #pragma unroll
        for (int mi = 0; mi < 2; mi++)
            #pragma unroll
            for (int hf = 0; hf < 2; hf++) {
                int r = warp_m*32 + mi*16 + grp + hf*8;
                red[r*2 + warp_n] = part[mi][hf];
            }
    }
    __syncthreads();
    if (tid < 128) {
        int n  = n0 + tid;
        int b  = n & 31;
        int ji = n >> 5;
        int ii = ji & 63, jj = ji >> 6;
        g_w[((size_t)(ii*B_ + b) * H_ + h) * T_ + jj] =
            (red[tid*2] + red[tid*2 + 1]) * 0.015625f;
    }
}

// ---------------- tf32 GEMM, cp.async 3-stage, 2 CTAs/SM ----------------------
#define GPA 36
#define GPB 136
template<int MI, bool BTRANS, int EPI>
__global__ __launch_bounds__(256, 2) void gemm_tf32(
    const float* __restrict__ A, const float* __restrict__ Bm,
    const float* __restrict__ bias, const float* __restrict__ add,
    float* __restrict__ C, int M, int N, int K)
{
    constexpr int MT = 64 * MI;
    constexpr int AW = MT * GPA;
    constexpr int BW = BTRANS ? 128 * GPA : 32 * GPB;
    extern __shared__ float sm[];
    const uint32_t smemb = smem_u32(sm);
    const uint32_t AsU = smemb;
    const uint32_t BsU = smemb + 3 * AW * 4;

    const int tid = threadIdx.x;
    const int lane = tid & 31, warp = tid >> 5;
    const int wm = warp >> 1, wn = warp & 1;
    const int grp = lane >> 2, tig = lane & 3;
    const int m0 = blockIdx.y * MT;
    const int n0 = blockIdx.x * 128;

    float acc[MI][8][4];
    #pragma unroll
    for (int i = 0; i < MI; i++)
        #pragma unroll
        for (int j = 0; j < 8; j++)
            #pragma unroll
            for (int k = 0; k < 4; k++) acc[i][j][k] = 0.f;

    const int S = K >> 5;

    auto load_stage = [&](int s, int buf) {
        uint32_t Ab = AsU + buf * AW * 4;
        #pragma unroll
        for (int c = 0; c < 2*MI; c++) {
            int idx = c * 256 + tid;
            int row = idx >> 3, cg = idx & 7;
            CP_ASYNC16(Ab + row*(GPA*4) + cg*16,
                       A + (size_t)(m0 + row) * K + s*32 + cg*4);
        }
        uint32_t Bb = BsU + buf * BW * 4;
        #pragma unroll
        for (int c = 0; c < 4; c++) {
            int idx = c * 256 + tid;
            if (BTRANS) {
                int nr = idx >> 3, cg = idx & 7;
                CP_ASYNC16(Bb + nr*(GPA*4) + cg*16,
                           Bm + (size_t)(n0 + nr) * K + s*32 + cg*4);
            } else {
                int kr = idx >> 5, ng = idx & 31;
                CP_ASYNC16(Bb + kr*(GPB*4) + ng*16,
                           Bm + (size_t)(s*32 + kr) * N + n0 + ng*4);
            }
        }
        CP_COMMIT();
    };

    load_stage(0, 0);
    load_stage(1, 1);

    for (int s = 0; s < S; s++) {
        if (s < S - 1) CP_WAIT1(); else CP_WAIT0();
        __syncthreads();
        if (s < S - 2) load_stage(s + 2, (s + 2) % 3);

        const float* Ab = sm + (s % 3) * AW;
        const float* Bb = sm + 3 * AW + (s % 3) * BW;
        #pragma unroll
        for (int ks = 0; ks < 4; ks++) {
            float a[MI][4];
            #pragma unroll
            for (int mi = 0; mi < MI; mi++) {
                int r = wm*(16*MI) + mi*16 + grp;
                int c = ks*8 + tig;
                a[mi][0] = Ab[r * GPA + c];
                a[mi][1] = Ab[(r + 8) * GPA + c];
                a[mi][2] = Ab[r * GPA + c + 4];
                a[mi][3] = Ab[(r + 8) * GPA + c + 4];
            }
            float b[8][2];
            #pragma unroll
            for (int nf = 0; nf < 8; nf++) {
                int n = wn*64 + nf*8 + grp;
                if (BTRANS) {
                    b[nf][0] = Bb[n * GPA + ks*8 + tig];
                    b[nf][1] = Bb[n * GPA + ks*8 + tig + 4];
                } else {
                    b[nf][0] = Bb[(ks*8 + tig) * GPB + n];
                    b[nf][1] = Bb[(ks*8 + tig + 4) * GPB + n];
                }
            }
            #pragma unroll
            for (int mi = 0; mi < MI; mi++)
                #pragma unroll
                for (int nf = 0; nf < 8; nf++)
                    mma_tf32(acc[mi][nf], a[mi], b[nf]);
        }
    }

    #pragma unroll
    for (int mi = 0; mi < MI; mi++)
        #pragma unroll
        for (int hf = 0; hf < 2; hf++) {
            int row = m0 + wm*(16*MI) + mi*16 + grp + hf*8;
            #pragma unroll
            for (int nf = 0; nf < 8; nf++) {
                int col = n0 + wn*64 + nf*8 + tig*2;
                float v0 = acc[mi][nf][hf*2 + 0] + bias[col];
                float v1 = acc[mi][nf][hf*2 + 1] + bias[col + 1];
                if (EPI == 1) { v0 = fmaxf(v0, 0.f); v1 = fmaxf(v1, 0.f); }
                if (EPI == 2) {
                    v0 += add[(size_t)row * N + col];
                    v1 += add[(size_t)row * N + col + 1];
                }
                *(float2*)(C + (size_t)row * N + col) = make_float2(v0, v1);
            }
        }
}

// ---------------- softmax + attn, one CTA per (b, h) --------------------------
__global__ __launch_bounds__(256) void softmax_attn_kernel()
{
    const int b = blockIdx.x, h = blockIdx.y;
    __shared__ float p[64][68];
    __shared__ float vs[64][68];
    const int t = threadIdx.x;
    const int i = t >> 2, q = t & 3;
    const int d0 = q * 16;

    {
        const float* src = g_qkv + (size_t)(i*B_ + b)*(3*E_) + 2*E_ + h*64 + d0;
        #pragma unroll
        for (int e = 0; e < 16; e += 4)
            *(float4*)&vs[i][d0 + e] = *(const float4*)(src + e);
    }
    {
        float w[16];
        const float* wr = g_w + ((size_t)(i*B_ + b)*H_ + h)*T_ + d0;
        #pragma unroll
        for (int e = 0; e < 16; e += 4) {
            float4 v4 = *(const float4*)(wr + e);
            w[e] = v4.x; w[e+1] = v4.y; w[e+2] = v4.z; w[e+3] = v4.w;
        }
        float mx = w[0];
        #pragma unroll
        for (int e = 1; e < 16; e++) mx = fmaxf(mx, w[e]);
        mx = fmaxf(mx, __shfl_xor_sync(~0u, mx, 1));
        mx = fmaxf(mx, __shfl_xor_sync(~0u, mx, 2));
        float s = 0.f;
        #pragma unroll
        for (int e = 0; e < 16; e++) { w[e] = expf(w[e] - mx); s += w[e]; }
        s += __shfl_xor_sync(~0u, s, 1);
        s += __shfl_xor_sync(~0u, s, 2);
        float inv = 1.f / s;
        #pragma unroll
        for (int e = 0; e < 16; e++) p[i][d0 + e] = w[e] * inv;
    }
    __syncthreads();

    float acc[16] = {};
    for (int j = 0; j < 64; j++) {
        float pij = p[i][j];
        #pragma unroll
        for (int e = 0; e < 16; e += 4) {
            float4 v4 = *(float4*)&vs[j][d0 + e];
            acc[e]   = fmaf(pij, v4.x, acc[e]);
            acc[e+1] = fmaf(pij, v4.y, acc[e+1]);
            acc[e+2] = fmaf(pij, v4.z, acc[e+2]);
            acc[e+3] = fmaf(pij, v4.w, acc[e+3]);
        }
    }
    float* dst = g_attn + (size_t)(i*B_ + b)*E_ + h*64 + d0;
    #pragma unroll
    for (int e = 0; e < 16; e += 4)
        *(float4*)(dst + e) = make_float4(acc[e], acc[e+1], acc[e+2], acc[e+3]);
}

// ---------------- layernorm ----------------------------------------------------
__global__ __launch_bounds__(256) void ln_kernel(
    const float* __restrict__ in, const float* __restrict__ g,
    const float* __restrict__ b, float* __restrict__ out)
{
    int row = blockIdx.x;
    const float* r = in + (size_t)row * E_;
    int t = threadIdx.x;
    float v0 = r[t], v1 = r[t + 256];
    float s = v0 + v1, sq = v0*v0 + v1*v1;
    #pragma unroll
    for (int o = 16; o; o >>= 1) {
        s  += __shfl_xor_sync(~0u, s,  o);
        sq += __shfl_xor_sync(~0u, sq, o);
    }
    __shared__ float ss[8], ssq[8];
    int w = t >> 5, l = t & 31;
    if (l == 0) { ss[w] = s; ssq[w] = sq; }
    __syncthreads();
    if (w == 0) {
        s  = (l < 8) ? ss[l]  : 0.f;
        sq = (l < 8) ? ssq[l] : 0.f;
        #pragma unroll
        for (int o = 4; o; o >>= 1) {
            s  += __shfl_xor_sync(~0u, s,  o);
            sq += __shfl_xor_sync(~0u, sq, o);
        }
        if (l == 0) { ss[0] = s; ssq[0] = sq; }
    }
    __syncthreads();
    float mu   = ss[0]  * (1.f / E_);
    float var  = ssq[0] * (1.f / E_) - mu * mu;
    float rstd = rsqrtf(var + 1e-5f);
    out[(size_t)row*E_ + t]       = (v0 - mu) * rstd * g[t]       + b[t];
    out[(size_t)row*E_ + t + 256] = (v1 - mu) * rstd * g[t + 256] + b[t + 256];
}

// ---------------- launch --------------------------------------------------------
extern "C" void kernel_launch(void* const* d_in, const int* in_sizes, int n_in,
                              void* d_out, int out_size)
{
    const float* x        = (const float*)d_in[0];
    const float* relation = (const float*)d_in[1];
    const float* in_w     = (const float*)d_in[2];
    const float* in_b     = (const float*)d_in[3];
    const float* rel_w    = (const float*)d_in[4];
    const float* rel_b    = (const float*)d_in[5];
    const float* out_w    = (const float*)d_in[6];
    const float* out_b    = (const float*)d_in[7];
    const float* fc1_w    = (const float*)d_in[8];
    const float* fc1_b    = (const float*)d_in[9];
    const float* fc2_w    = (const float*)d_in[10];
    const float* fc2_b    = (const float*)d_in[11];
    const float* ln1_g    = (const float*)d_in[12];
    const float* ln1_b    = (const float*)d_in[13];
    const float* ln2_g    = (const float*)d_in[14];
    const float* ln2_b    = (const float*)d_in[15];
    float* out = (float*)d_out;

    const int SM_BT64  = 3 * (64*GPA  + 128*GPA) * 4;
    const int SM_BN64  = 3 * (64*GPA  + 32*GPB) * 4;
    const int SM_BN128 = 3 * (128*GPA + 32*GPB) * 4;

    static float *p_qkv = nullptr, *p_attn, *p_ao, *p_h, *p_f1, *p_f2;
    static __nv_bfloat16* p_arel;
    static cudaStream_t s_side;
    static cudaEvent_t ev_fork, ev_c[NCHUNK];
    if (!p_qkv) {
        cudaGetSymbolAddress((void**)&p_qkv,  g_qkv);
        cudaGetSymbolAddress((void**)&p_attn, g_attn);
        cudaGetSymbolAddress((void**)&p_ao,   g_ao);
        cudaGetSymbolAddress((void**)&p_h,    g_h);
        cudaGetSymbolAddress((void**)&p_f1,   g_f1);
        cudaGetSymbolAddress((void**)&p_f2,   g_f2);
        cudaGetSymbolAddress((void**)&p_arel, g_arel);
        cudaFuncSetAttribute(relw_mma, cudaFuncAttributeMaxDynamicSharedMemorySize, RELW_SMEM);
        cudaFuncSetAttribute(gemm_tf32<1, true, 0>,  cudaFuncAttributeMaxDynamicSharedMemorySize, SM_BT64);
        cudaFuncSetAttribute(gemm_tf32<1, false, 2>, cudaFuncAttributeMaxDynamicSharedMemorySize, SM_BN64);
        cudaFuncSetAttribute(gemm_tf32<2, false, 1>, cudaFuncAttributeMaxDynamicSharedMemorySize, SM_BN128);
        cudaStreamCreateWithFlags(&s_side, cudaStreamNonBlocking);
        cudaEventCreateWithFlags(&ev_fork, cudaEventDisableTiming);
        for (int c = 0; c < NCHUNK; c++)
            cudaEventCreateWithFlags(&ev_c[c], cudaEventDisableTiming);
    }

    dim3 blk(256);

    // ---- fork: chunked cvt_rel on side stream ----------------------------------
    cudaEventRecord(ev_fork, 0);
    cudaStreamWaitEvent(s_side, ev_fork, 0);
    const size_t CELEMS = (size_t)CROWS * E_;          // elements per chunk
    for (int c = 0; c < NCHUNK; c++) {
        cvt_rel<<<CELEMS / (8 * 256), 256, 0, s_side>>>(relation + c * CELEMS,
                                                        p_arel + c * CELEMS);
        cudaEventRecord(ev_c[c], s_side);
    }

    // main stream: weights + qkv (must precede relw chunk 0)
    build_bw<<<1024, 256>>>(rel_w);
    gemm_tf32<1, true, 0><<<dim3(1536/128, TB_/64), blk, SM_BT64>>>(x, in_w, in_b, nullptr, p_qkv, TB_, 3*E_, E_);

    // 2. relation GEMM chunks, each gated on its cvt chunk
    for (int c = 0; c < NCHUNK; c++) {
        cudaStreamWaitEvent(0, ev_c[c], 0);
        relw_mma<<<dim3(H_, CROWS/128), blk, RELW_SMEM>>>(rel_b, c * CROWS);
    }

    // 3. softmax + attn, CTA per (b,h)
    softmax_attn_kernel<<<dim3(B_, H_), 256>>>();

    // 4. out proj + residual
    gemm_tf32<1, false, 2><<<dim3(E_/128, TB_/64), blk, SM_BN64>>>(p_attn, out_w, out_b, x, p_ao, TB_, E_, E_);

    // 5. LN1
    ln_kernel<<<TB_, 256>>>(p_ao, ln1_g, ln1_b, p_h);

    // 6. fc1 + relu
    gemm_tf32<2, false, 1><<<dim3(F_/128, TB_/128), blk, SM_BN128>>>(p_h, fc1_w, fc1_b, nullptr, p_f1, TB_, F_, E_);

    // 7. fc2 + residual h
    gemm_tf32<1, false, 2><<<dim3(E_/128, TB_/64), blk, SM_BN64>>>(p_f1, fc2_w, fc2_b, p_h, p_f2, TB_, E_, F_);

    // 8. LN2 -> out
    ln_kernel<<<TB_, 256>>>(p_f2, ln2_g, ln2_b, out);
}

// round 13
// speedup vs baseline: 1.0280x; 1.0280x over previous
#include <cuda_runtime.h>
#include <cuda_bf16.h>
#include <cstdint>

#define T_  64
#define B_  32
#define E_  512
#define H_  8
#define F_  2048
#define TB_ (T_*B_)        // 2048
#define ROWS_ (T_*T_*B_)   // 131072

// ---------------- scratch ----------------------------------------------------
__device__ float g_qkv[TB_ * 3 * E_];
__device__ float g_w[TB_ * H_ * T_];
__device__ float g_attn[TB_ * E_];
__device__ float g_ao[TB_ * E_];
__device__ float g_h[TB_ * E_];
__device__ float g_f1[TB_ * F_];
__device__ float g_f2[TB_ * E_];
__device__ __nv_bfloat16 g_arel[(size_t)ROWS_ * E_];   // relation in bf16 (134MB)
__device__ __nv_bfloat16 g_bw[H_ * E_ * 128];          // [h][k][2d interleaved ra/rb]

// ---------------- helpers ------------------------------------------------------
__device__ __forceinline__ uint32_t smem_u32(const void* p) {
    return (uint32_t)__cvta_generic_to_shared(p);
}
__device__ __forceinline__ void ldsm_x4(uint32_t& r0, uint32_t& r1, uint32_t& r2, uint32_t& r3, uint32_t a) {
    asm volatile("ldmatrix.sync.aligned.m8n8.x4.shared.b16 {%0,%1,%2,%3},[%4];"
                 : "=r"(r0), "=r"(r1), "=r"(r2), "=r"(r3) : "r"(a));
}
__device__ __forceinline__ void ldsm_x4_t(uint32_t& r0, uint32_t& r1, uint32_t& r2, uint32_t& r3, uint32_t a) {
    asm volatile("ldmatrix.sync.aligned.m8n8.x4.trans.shared.b16 {%0,%1,%2,%3},[%4];"
                 : "=r"(r0), "=r"(r1), "=r"(r2), "=r"(r3) : "r"(a));
}
__device__ __forceinline__ void mma16816(float* c, const uint32_t* a, const uint32_t* b) {
    asm volatile("mma.sync.aligned.m16n8k16.row.col.f32.bf16.bf16.f32 "
                 "{%0,%1,%2,%3},{%4,%5,%6,%7},{%8,%9},{%0,%1,%2,%3};"
                 : "+f"(c[0]), "+f"(c[1]), "+f"(c[2]), "+f"(c[3])
                 : "r"(a[0]), "r"(a[1]), "r"(a[2]), "r"(a[3]), "r"(b[0]), "r"(b[1]));
}
__device__ __forceinline__ void mma_tf32(float* c, const float* a, const float* b) {
    asm volatile("mma.sync.aligned.m16n8k8.row.col.f32.tf32.tf32.f32 "
                 "{%0,%1,%2,%3},{%4,%5,%6,%7},{%8,%9},{%0,%1,%2,%3};"
                 : "+f"(c[0]), "+f"(c[1]), "+f"(c[2]), "+f"(c[3])
                 : "r"(__float_as_uint(a[0])), "r"(__float_as_uint(a[1])),
                   "r"(__float_as_uint(a[2])), "r"(__float_as_uint(a[3])),
                   "r"(__float_as_uint(b[0])), "r"(__float_as_uint(b[1])));
}
__device__ __forceinline__ uint32_t f2bf2(float x, float y) {
    __nv_bfloat162 t = __floats2bfloat162_rn(x, y);
    return *reinterpret_cast<uint32_t*>(&t);
}
#define CP_ASYNC16(saddr, gptr) \
    asm volatile("cp.async.cg.shared.global [%0], [%1], 16;" :: "r"(saddr), "l"(gptr) : "memory")
#define CP_COMMIT() asm volatile("cp.async.commit_group;" ::: "memory")
#define CP_WAIT1()  asm volatile("cp.async.wait_group 1;" ::: "memory")
#define CP_WAIT0()  asm volatile("cp.async.wait_group 0;" ::: "memory")

// ---------------- prepass: relation fp32 -> bf16 ------------------------------
__global__ __launch_bounds__(256) void cvt_rel(const float* __restrict__ rel,
                                               __nv_bfloat16* __restrict__ dst)
{
    size_t i = ((size_t)blockIdx.x * 256 + threadIdx.x) * 8;
    float4 a = *(const float4*)(rel + i);
    float4 b = *(const float4*)(rel + i + 4);
    uint4 v = make_uint4(f2bf2(a.x, a.y), f2bf2(a.z, a.w),
                         f2bf2(b.x, b.y), f2bf2(b.z, b.w));
    *(uint4*)((char*)dst + i * 2) = v;
}

// ---------------- prepass: interleaved bf16 weight tiles [h][k][128] ----------
__global__ __launch_bounds__(256) void build_bw(const float* __restrict__ relw)
{
    int idx = blockIdx.x * 256 + threadIdx.x;    // 262144
    int d = idx & 63;
    int k = (idx >> 6) & 511;
    int h = idx >> 15;
    g_bw[((size_t)h*E_ + k) * 128 + 2*d    ] = __float2bfloat16(relw[(size_t)k*(2*E_) + h*64 + d]);
    g_bw[((size_t)h*E_ + k) * 128 + 2*d + 1] = __float2bfloat16(relw[(size_t)k*(2*E_) + E_ + h*64 + d]);
}

// ---------------- fused relation GEMM (bf16 HMMA, 3-stage, 2 CTAs/SM) ---------
#define RSA_STRIDE 16384
#define RSB_BASE   49152
#define RSB_STRIDE 16384
#define RELW_SMEM  98304
__global__ void __launch_bounds__(256, 2) relw_mma(const float* __restrict__ relb)
{
    extern __shared__ char smem[];
    const uint32_t AsBase = smem_u32(smem);
    const uint32_t BsBase = AsBase + RSB_BASE;
    float* red = (float*)smem;

    const int h   = blockIdx.x;
    const int n0  = blockIdx.y * 128;
    const int tid = threadIdx.x;
    const int lane = tid & 31, warp = tid >> 5;
    const int warp_m = warp >> 1, warp_n = warp & 1;

    float acc[2][8][4];
    #pragma unroll
    for (int i = 0; i < 2; i++)
        #pragma unroll
        for (int j = 0; j < 8; j++)
            #pragma unroll
            for (int k = 0; k < 4; k++) acc[i][j][k] = 0.f;

    const __nv_bfloat16* Ag = g_arel + (size_t)n0 * E_;
    const __nv_bfloat16* Bg = g_bw + (size_t)h * E_ * 128;

    auto load_stage = [&](int s, int buf) {
        uint32_t Ab = AsBase + buf * RSA_STRIDE;
        #pragma unroll
        for (int c = 0; c < 4; c++) {
            int idx = c * 256 + tid;
            int row = idx >> 3, cg = idx & 7;
            CP_ASYNC16(Ab + row*128 + (((cg ^ (row & 7)) << 4)),
                       Ag + (size_t)row * E_ + s*64 + cg*8);
        }
        uint32_t Bb = BsBase + buf * RSB_STRIDE;
        #pragma unroll
        for (int c = 0; c < 4; c++) {
            int idx = c * 256 + tid;
            int kr = idx >> 4, ng = idx & 15;
            CP_ASYNC16(Bb + kr*256 + (((ng ^ (kr & 7)) << 4)),
                       Bg + (size_t)(s*64 + kr) * 128 + ng*8);
        }
        CP_COMMIT();
    };

    load_stage(0, 0);
    load_stage(1, 1);

    const int a_r  = warp_m*32 + (lane & 15);
    const int a_kc = (lane >> 4) << 3;
    const int b_kr = lane & 15;
    const int b_nc = warp_n*64 + ((lane >> 4) << 3);

    #pragma unroll
    for (int s = 0; s < 8; s++) {
        if (s < 7) CP_WAIT1(); else CP_WAIT0();
        __syncthreads();
        if (s < 6) load_stage(s + 2, (s + 2) % 3);

        const uint32_t Ab = AsBase + (s % 3) * RSA_STRIDE;
        const uint32_t Bb = BsBase + (s % 3) * RSB_STRIDE;

        #pragma unroll
        for (int ks = 0; ks < 4; ks++) {
            uint32_t a[2][4];
            #pragma unroll
            for (int mi = 0; mi < 2; mi++) {
                int r  = a_r + mi*16;
                int kc = a_kc + ks*16;
                ldsm_x4(a[mi][0], a[mi][1], a[mi][2], a[mi][3],
                        Ab + r*128 + ((((kc >> 3) ^ (r & 7)) << 4)));
            }
            uint32_t b[8][2];
            #pragma unroll
            for (int g = 0; g < 4; g++) {
                int krow = b_kr + ks*16;
                int ncol = b_nc + g*16;
                ldsm_x4_t(b[2*g][0], b[2*g][1], b[2*g+1][0], b[2*g+1][1],
                          Bb + krow*256 + ((((ncol >> 3) ^ (krow & 7)) << 4)));
            }
            #pragma unroll
            for (int mi = 0; mi < 2; mi++)
                #pragma unroll
                for (int nf = 0; nf < 8; nf++)
                    mma16816(acc[mi][nf], a[mi], b[nf]);
        }
    }

    // ---- fused epilogue --------------------------------------------------------
    const int tig = lane & 3, grp = lane >> 2;
    float part[2][2] = {{0.f, 0.f}, {0.f, 0.f}};
    #pragma unroll
    for (int nf = 0; nf < 8; nf++) {
        int d = warp_n*32 + nf*4 + tig;
        float bra = relb[h*64 + d];
        float brb = relb[E_ + h*64 + d];
        #pragma unroll
        for (int mi = 0; mi < 2; mi++)
            #pragma unroll
            for (int hf = 0; hf < 2; hf++) {
                int r  = warp_m*32 + mi*16 + grp + hf*8;
                int n  = n0 + r;
                int b  = n & 31;
                int ji = n >> 5;
                int ii = ji & 63, jj = ji >> 6;
                float q = g_qkv[(size_t)(ii*B_ + b) * (3*E_) + h*64 + d];
                float k = g_qkv[(size_t)(jj*B_ + b) * (3*E_) + E_ + h*64 + d];
                part[mi][hf] += (acc[mi][nf][hf*2+0] + bra + q) * (acc[mi][nf][hf*2+1] + brb + k);
            }
    }
    #pragma unroll
    for (int mi = 0; mi < 2; mi++)
        #pragma unroll
        for (int hf = 0; hf < 2; hf++) {
            float v = part[mi][hf];
            v += __shfl_xor_sync(~0u, v, 1);
            v += __shfl_xor_sync(~0u, v, 2);
            part[mi][hf] = v;
        }
    __syncthreads();
    if (tig == 0) {
        #pragma unroll
        for (int mi = 0; mi < 2; mi++)
            #pragma unroll
            for (int hf = 0; hf < 2; hf++) {
                int r = warp_m*32 + mi*16 + grp + hf*8;
                red[r*2 + warp_n] = part[mi][hf];
            }
    }
    __syncthreads();
    if (tid < 128) {
        int n  = n0 + tid;
        int b  = n & 31;
        int ji = n >> 5;
        int ii = ji & 63, jj = ji >> 6;
        g_w[((size_t)(ii*B_ + b) * H_ + h) * T_ + jj] =
            (red[tid*2] + red[tid*2 + 1]) * 0.015625f;
    }
}

// ---------------- tf32 GEMM, cp.async 3-stage, 2 CTAs/SM ----------------------
#define GPA 36
#define GPB 136
template<int MI, bool BTRANS, int EPI>
__global__ __launch_bounds__(256, 2) void gemm_tf32(
    const float* __restrict__ A, const float* __restrict__ Bm,
    const float* __restrict__ bias, const float* __restrict__ add,
    float* __restrict__ C, int M, int N, int K)
{
    constexpr int MT = 64 * MI;
    constexpr int AW = MT * GPA;
    constexpr int BW = BTRANS ? 128 * GPA : 32 * GPB;
    extern __shared__ float sm[];
    const uint32_t smemb = smem_u32(sm);
    const uint32_t AsU = smemb;
    const uint32_t BsU = smemb + 3 * AW * 4;

    const int tid = threadIdx.x;
    const int lane = tid & 31, warp = tid >> 5;
    const int wm = warp >> 1, wn = warp & 1;
    const int grp = lane >> 2, tig = lane & 3;
    const int m0 = blockIdx.y * MT;
    const int n0 = blockIdx.x * 128;

    float acc[MI][8][4];
    #pragma unroll
    for (int i = 0; i < MI; i++)
        #pragma unroll
        for (int j = 0; j < 8; j++)
            #pragma unroll
            for (int k = 0; k < 4; k++) acc[i][j][k] = 0.f;

    const int S = K >> 5;

    auto load_stage = [&](int s, int buf) {
        uint32_t Ab = AsU + buf * AW * 4;
        #pragma unroll
        for (int c = 0; c < 2*MI; c++) {
            int idx = c * 256 + tid;
            int row = idx >> 3, cg = idx & 7;
            CP_ASYNC16(Ab + row*(GPA*4) + cg*16,
                       A + (size_t)(m0 + row) * K + s*32 + cg*4);
        }
        uint32_t Bb = BsU + buf * BW * 4;
        #pragma unroll
        for (int c = 0; c < 4; c++) {
            int idx = c * 256 + tid;
            if (BTRANS) {
                int nr = idx >> 3, cg = idx & 7;
                CP_ASYNC16(Bb + nr*(GPA*4) + cg*16,
                           Bm + (size_t)(n0 + nr) * K + s*32 + cg*4);
            } else {
                int kr = idx >> 5, ng = idx & 31;
                CP_ASYNC16(Bb + kr*(GPB*4) + ng*16,
                           Bm + (size_t)(s*32 + kr) * N + n0 + ng*4);
            }
        }
        CP_COMMIT();
    };

    load_stage(0, 0);
    load_stage(1, 1);

    for (int s = 0; s < S; s++) {
        if (s < S - 1) CP_WAIT1(); else CP_WAIT0();
        __syncthreads();
        if (s < S - 2) load_stage(s + 2, (s + 2) % 3);

        const float* Ab = sm + (s % 3) * AW;
        const float* Bb = sm + 3 * AW + (s % 3) * BW;
        #pragma unroll
        for (int ks = 0; ks < 4; ks++) {
            float a[MI][4];
            #pragma unroll
            for (int mi = 0; mi < MI; mi++) {
                int r = wm*(16*MI) + mi*16 + grp;
                int c = ks*8 + tig;
                a[mi][0] = Ab[r * GPA + c];
                a[mi][1] = Ab[(r + 8) * GPA + c];
                a[mi][2] = Ab[r * GPA + c + 4];
                a[mi][3] = Ab[(r + 8) * GPA + c + 4];
            }
            float b[8][2];
            #pragma unroll
            for (int nf = 0; nf < 8; nf++) {
                int n = wn*64 + nf*8 + grp;
                if (BTRANS) {
                    b[nf][0] = Bb[n * GPA + ks*8 + tig];
                    b[nf][1] = Bb[n * GPA + ks*8 + tig + 4];
                } else {
                    b[nf][0] = Bb[(ks*8 + tig) * GPB + n];
                    b[nf][1] = Bb[(ks*8 + tig + 4) * GPB + n];
                }
            }
            #pragma unroll
            for (int mi = 0; mi < MI; mi++)
                #pragma unroll
                for (int nf = 0; nf < 8; nf++)
                    mma_tf32(acc[mi][nf], a[mi], b[nf]);
        }
    }

    #pragma unroll
    for (int mi = 0; mi < MI; mi++)
        #pragma unroll
        for (int hf = 0; hf < 2; hf++) {
            int row = m0 + wm*(16*MI) + mi*16 + grp + hf*8;
            #pragma unroll
            for (int nf = 0; nf < 8; nf++) {
                int col = n0 + wn*64 + nf*8 + tig*2;
                float v0 = acc[mi][nf][hf*2 + 0] + bias[col];
                float v1 = acc[mi][nf][hf*2 + 1] + bias[col + 1];
                if (EPI == 1) { v0 = fmaxf(v0, 0.f); v1 = fmaxf(v1, 0.f); }
                if (EPI == 2) {
                    v0 += add[(size_t)row * N + col];
                    v1 += add[(size_t)row * N + col + 1];
                }
                *(float2*)(C + (size_t)row * N + col) = make_float2(v0, v1);
            }
        }
}

// ---------------- tf32 GEMM 64x64 tile (small-N: out-proj, fc2) ---------------
// 8 warps 2(m)x4(n), warp tile 32x16, acc=16 regs. K-stage 32, 3-stage cp.async.
#define GPB2 72
template<int EPI>
__global__ __launch_bounds__(256, 2) void gemm_tf32_n64(
    const float* __restrict__ A, const float* __restrict__ Bm,
    const float* __restrict__ bias, const float* __restrict__ add,
    float* __restrict__ C, int M, int N, int K)
{
    constexpr int AW = 64 * GPA;   // 2304 words
    constexpr int BW = 32 * GPB2;  // 2304 words
    extern __shared__ float sm[];
    const uint32_t smemb = smem_u32(sm);
    const uint32_t AsU = smemb;
    const uint32_t BsU = smemb + 3 * AW * 4;

    const int tid = threadIdx.x;
    const int lane = tid & 31, warp = tid >> 5;
    const int wm = warp >> 2, wn = warp & 3;        // 2 x 4
    const int grp = lane >> 2, tig = lane & 3;
    const int m0 = blockIdx.y * 64;
    const int n0 = blockIdx.x * 64;

    float acc[2][2][4];
    #pragma unroll
    for (int i = 0; i < 2; i++)
        #pragma unroll
        for (int j = 0; j < 2; j++)
            #pragma unroll
            for (int k = 0; k < 4; k++) acc[i][j][k] = 0.f;

    const int S = K >> 5;

    auto load_stage = [&](int s, int buf) {
        uint32_t Ab = AsU + buf * AW * 4;
        #pragma unroll
        for (int c = 0; c < 2; c++) {
            int idx = c * 256 + tid;             // 512 chunks (64 rows x 32 k)
            int row = idx >> 3, cg = idx & 7;
            CP_ASYNC16(Ab + row*(GPA*4) + cg*16,
                       A + (size_t)(m0 + row) * K + s*32 + cg*4);
        }
        uint32_t Bb = BsU + buf * BW * 4;
        #pragma unroll
        for (int c = 0; c < 2; c++) {
            int idx = c * 256 + tid;             // 512 chunks (32 k-rows x 64 n)
            int kr = idx >> 4, ng = idx & 15;
            CP_ASYNC16(Bb + kr*(GPB2*4) + ng*16,
                       Bm + (size_t)(s*32 + kr) * N + n0 + ng*4);
        }
        CP_COMMIT();
    };

    load_stage(0, 0);
    load_stage(1, 1);

    for (int s = 0; s < S; s++) {
        if (s < S - 1) CP_WAIT1(); else CP_WAIT0();
        __syncthreads();
        if (s < S - 2) load_stage(s + 2, (s + 2) % 3);

        const float* Ab = sm + (s % 3) * AW;
        const float* Bb = sm + 3 * AW + (s % 3) * BW;
        #pragma unroll
        for (int ks = 0; ks < 4; ks++) {
            float a[2][4];
            #pragma unroll
            for (int mi = 0; mi < 2; mi++) {
                int r = wm*32 + mi*16 + grp;
                int c = ks*8 + tig;
                a[mi][0] = Ab[r * GPA + c];
                a[mi][1] = Ab[(r + 8) * GPA + c];
                a[mi][2] = Ab[r * GPA + c + 4];
                a[mi][3] = Ab[(r + 8) * GPA + c + 4];
            }
            float b[2][2];
            #pragma unroll
            for (int nf = 0; nf < 2; nf++) {
                int n = wn*16 + nf*8 + grp;
                b[nf][0] = Bb[(ks*8 + tig) * GPB2 + n];
                b[nf][1] = Bb[(ks*8 + tig + 4) * GPB2 + n];
            }
            #pragma unroll
            for (int mi = 0; mi < 2; mi++)
                #pragma unroll
                for (int nf = 0; nf < 2; nf++)
                    mma_tf32(acc[mi][nf], a[mi], b[nf]);
        }
    }

    #pragma unroll
    for (int mi = 0; mi < 2; mi++)
        #pragma unroll
        for (int hf = 0; hf < 2; hf++) {
            int row = m0 + wm*32 + mi*16 + grp + hf*8;
            #pragma unroll
            for (int nf = 0; nf < 2; nf++) {
                int col = n0 + wn*16 + nf*8 + tig*2;
                float v0 = acc[mi][nf][hf*2 + 0] + bias[col];
                float v1 = acc[mi][nf][hf*2 + 1] + bias[col + 1];
                if (EPI == 1) { v0 = fmaxf(v0, 0.f); v1 = fmaxf(v1, 0.f); }
                if (EPI == 2) {
                    v0 += add[(size_t)row * N + col];
                    v1 += add[(size_t)row * N + col + 1];
                }
                *(float2*)(C + (size_t)row * N + col) = make_float2(v0, v1);
            }
        }
}

// ---------------- softmax + attn, one CTA per (b, h) --------------------------
__global__ __launch_bounds__(256) void softmax_attn_kernel()
{
    const int b = blockIdx.x, h = blockIdx.y;
    __shared__ float p[64][68];
    __shared__ float vs[64][68];
    const int t = threadIdx.x;
    const int i = t >> 2, q = t & 3;
    const int d0 = q * 16;

    {
        const float* src = g_qkv + (size_t)(i*B_ + b)*(3*E_) + 2*E_ + h*64 + d0;
        #pragma unroll
        for (int e = 0; e < 16; e += 4)
            *(float4*)&vs[i][d0 + e] = *(const float4*)(src + e);
    }
    {
        float w[16];
        const float* wr = g_w + ((size_t)(i*B_ + b)*H_ + h)*T_ + d0;
        #pragma unroll
        for (int e = 0; e < 16; e += 4) {
            float4 v4 = *(const float4*)(wr + e);
            w[e] = v4.x; w[e+1] = v4.y; w[e+2] = v4.z; w[e+3] = v4.w;
        }
        float mx = w[0];
        #pragma unroll
        for (int e = 1; e < 16; e++) mx = fmaxf(mx, w[e]);
        mx = fmaxf(mx, __shfl_xor_sync(~0u, mx, 1));
        mx = fmaxf(mx, __shfl_xor_sync(~0u, mx, 2));
        float s = 0.f;
        #pragma unroll
        for (int e = 0; e < 16; e++) { w[e] = expf(w[e] - mx); s += w[e]; }
        s += __shfl_xor_sync(~0u, s, 1);
        s += __shfl_xor_sync(~0u, s, 2);
        float inv = 1.f / s;
        #pragma unroll
        for (int e = 0; e < 16; e++) p[i][d0 + e] = w[e] * inv;
    }
    __syncthreads();

    float acc[16] = {};
    for (int j = 0; j < 64; j++) {
        float pij = p[i][j];
        #pragma unroll
        for (int e = 0; e < 16; e += 4) {
            float4 v4 = *(float4*)&vs[j][d0 + e];
            acc[e]   = fmaf(pij, v4.x, acc[e]);
            acc[e+1] = fmaf(pij, v4.y, acc[e+1]);
            acc[e+2] = fmaf(pij, v4.z, acc[e+2]);
            acc[e+3] = fmaf(pij, v4.w, acc[e+3]);
        }
    }
    float* dst = g_attn + (size_t)(i*B_ + b)*E_ + h*64 + d0;
    #pragma unroll
    for (int e = 0; e < 16; e += 4)
        *(float4*)(dst + e) = make_float4(acc[e], acc[e+1], acc[e+2], acc[e+3]);
}

// ---------------- layernorm ----------------------------------------------------
__global__ __launch_bounds__(256) void ln_kernel(
    const float* __restrict__ in, const float* __restrict__ g,
    const float* __restrict__ b, float* __restrict__ out)
{
    int row = blockIdx.x;
    const float* r = in + (size_t)row * E_;
    int t = threadIdx.x;
    float v0 = r[t], v1 = r[t + 256];
    float s = v0 + v1, sq = v0*v0 + v1*v1;
    #pragma unroll
    for (int o = 16; o; o >>= 1) {
        s  += __shfl_xor_sync(~0u, s,  o);
        sq += __shfl_xor_sync(~0u, sq, o);
    }
    __shared__ float ss[8], ssq[8];
    int w = t >> 5, l = t & 31;
    if (l == 0) { ss[w] = s; ssq[w] = sq; }
    __syncthreads();
    if (w == 0) {
        s  = (l < 8) ? ss[l]  : 0.f;
        sq = (l < 8) ? ssq[l] : 0.f;
        #pragma unroll
        for (int o = 4; o; o >>= 1) {
            s  += __shfl_xor_sync(~0u, s,  o);
            sq += __shfl_xor_sync(~0u, sq, o);
        }
        if (l == 0) { ss[0] = s; ssq[0] = sq; }
    }
    __syncthreads();
    float mu   = ss[0]  * (1.f / E_);
    float var  = ssq[0] * (1.f / E_) - mu * mu;
    float rstd = rsqrtf(var + 1e-5f);
    out[(size_t)row*E_ + t]       = (v0 - mu) * rstd * g[t]       + b[t];
    out[(size_t)row*E_ + t + 256] = (v1 - mu) * rstd * g[t + 256] + b[t + 256];
}

// ---------------- launch --------------------------------------------------------
extern "C" void kernel_launch(void* const* d_in, const int* in_sizes, int n_in,
                              void* d_out, int out_size)
{
    const float* x        = (const float*)d_in[0];
    const float* relation = (const float*)d_in[1];
    const float* in_w     = (const float*)d_in[2];
    const float* in_b     = (const float*)d_in[3];
    const float* rel_w    = (const float*)d_in[4];
    const float* rel_b    = (const float*)d_in[5];
    const float* out_w    = (const float*)d_in[6];
    const float* out_b    = (const float*)d_in[7];
    const float* fc1_w    = (const float*)d_in[8];
    const float* fc1_b    = (const float*)d_in[9];
    const float* fc2_w    = (const float*)d_in[10];
    const float* fc2_b    = (const float*)d_in[11];
    const float* ln1_g    = (const float*)d_in[12];
    const float* ln1_b    = (const float*)d_in[13];
    const float* ln2_g    = (const float*)d_in[14];
    const float* ln2_b    = (const float*)d_in[15];
    float* out = (float*)d_out;

    const int SM_BT64  = 3 * (64*GPA  + 128*GPA) * 4;   // qkv
    const int SM_BN128 = 3 * (128*GPA + 32*GPB) * 4;    // fc1
    const int SM_N64   = 3 * (64*GPA  + 32*GPB2) * 4;   // out/fc2 (55296)

    static float *p_qkv = nullptr, *p_attn, *p_ao, *p_h, *p_f1, *p_f2;
    static __nv_bfloat16* p_arel;
    static cudaStream_t s_side;
    static cudaEvent_t ev_fork, ev_join;
    if (!p_qkv) {
        cudaGetSymbolAddress((void**)&p_qkv,  g_qkv);
        cudaGetSymbolAddress((void**)&p_attn, g_attn);
        cudaGetSymbolAddress((void**)&p_ao,   g_ao);
        cudaGetSymbolAddress((void**)&p_h,    g_h);
        cudaGetSymbolAddress((void**)&p_f1,   g_f1);
        cudaGetSymbolAddress((void**)&p_f2,   g_f2);
        cudaGetSymbolAddress((void**)&p_arel, g_arel);
        cudaFuncSetAttribute(relw_mma, cudaFuncAttributeMaxDynamicSharedMemorySize, RELW_SMEM);
        cudaFuncSetAttribute(gemm_tf32<1, true, 0>,  cudaFuncAttributeMaxDynamicSharedMemorySize, SM_BT64);
        cudaFuncSetAttribute(gemm_tf32<2, false, 1>, cudaFuncAttributeMaxDynamicSharedMemorySize, SM_BN128);
        cudaFuncSetAttribute(gemm_tf32_n64<2>, cudaFuncAttributeMaxDynamicSharedMemorySize, SM_N64);
        cudaStreamCreateWithFlags(&s_side, cudaStreamNonBlocking);
        cudaEventCreateWithFlags(&ev_fork, cudaEventDisableTiming);
        cudaEventCreateWithFlags(&ev_join, cudaEventDisableTiming);
    }

    dim3 blk(256);

    // ---- fork: cvt_rel on side stream (fully before relw; overlaps bw+qkv only)
    cudaEventRecord(ev_fork, 0);
    cudaStreamWaitEvent(s_side, ev_fork, 0);
    cvt_rel<<<ROWS_ * E_ / (8 * 256), 256, 0, s_side>>>(relation, p_arel);
    cudaEventRecord(ev_join, s_side);

    build_bw<<<1024, 256>>>(rel_w);
    gemm_tf32<1, true, 0><<<dim3(1536/128, TB_/64), blk, SM_BT64>>>(x, in_w, in_b, nullptr, p_qkv, TB_, 3*E_, E_);

    cudaStreamWaitEvent(0, ev_join, 0);

    // 2. relation GEMM (bf16 HMMA) + fused logits
    relw_mma<<<dim3(H_, ROWS_/128), blk, RELW_SMEM>>>(rel_b);

    // 3. softmax + attn, CTA per (b,h)
    softmax_attn_kernel<<<dim3(B_, H_), 256>>>();

    // 4. out proj + residual       (64x64 tiles: grid 256)
    gemm_tf32_n64<2><<<dim3(E_/64, TB_/64), blk, SM_N64>>>(p_attn, out_w, out_b, x, p_ao, TB_, E_, E_);

    // 5. LN1
    ln_kernel<<<TB_, 256>>>(p_ao, ln1_g, ln1_b, p_h);

    // 6. fc1 + relu                (128x128 tiles: grid 256)
    gemm_tf32<2, false, 1><<<dim3(F_/128, TB_/128), blk, SM_BN128>>>(p_h, fc1_w, fc1_b, nullptr, p_f1, TB_, F_, E_);

    // 7. fc2 + residual h          (64x64 tiles: grid 256)
    gemm_tf32_n64<2><<<dim3(E_/64, TB_/64), blk, SM_N64>>>(p_f1, fc2_w, fc2_b, p_h, p_f2, TB_, E_, F_);

    // 8. LN2 -> out
    ln_kernel<<<TB_, 256>>>(p_f2, ln2_g, ln2_b, out);
}

// round 14
// speedup vs baseline: 1.0337x; 1.0055x over previous
#include <cuda_runtime.h>
#include <cuda_bf16.h>
#include <cstdint>

#define T_  64
#define B_  32
#define E_  512
#define H_  8
#define F_  2048
#define TB_ (T_*B_)        // 2048
#define ROWS_ (T_*T_*B_)   // 131072

// ---------------- scratch ----------------------------------------------------
__device__ float g_qkv[TB_ * 3 * E_];
__device__ float g_w[TB_ * H_ * T_];
__device__ float g_attn[TB_ * E_];
__device__ float g_ao[TB_ * E_];
__device__ float g_h[TB_ * E_];
__device__ float g_f1[TB_ * F_];
__device__ float g_f2[TB_ * E_];
__device__ __nv_bfloat16 g_arel[(size_t)ROWS_ * E_];   // relation in bf16 (134MB)
__device__ __nv_bfloat16 g_bw[H_ * E_ * 128];          // [h][k][2d interleaved ra/rb]

// ---------------- helpers ------------------------------------------------------
__device__ __forceinline__ uint32_t smem_u32(const void* p) {
    return (uint32_t)__cvta_generic_to_shared(p);
}
__device__ __forceinline__ void ldsm_x4(uint32_t& r0, uint32_t& r1, uint32_t& r2, uint32_t& r3, uint32_t a) {
    asm volatile("ldmatrix.sync.aligned.m8n8.x4.shared.b16 {%0,%1,%2,%3},[%4];"
                 : "=r"(r0), "=r"(r1), "=r"(r2), "=r"(r3) : "r"(a));
}
__device__ __forceinline__ void ldsm_x4_t(uint32_t& r0, uint32_t& r1, uint32_t& r2, uint32_t& r3, uint32_t a) {
    asm volatile("ldmatrix.sync.aligned.m8n8.x4.trans.shared.b16 {%0,%1,%2,%3},[%4];"
                 : "=r"(r0), "=r"(r1), "=r"(r2), "=r"(r3) : "r"(a));
}
__device__ __forceinline__ void mma16816(float* c, const uint32_t* a, const uint32_t* b) {
    asm volatile("mma.sync.aligned.m16n8k16.row.col.f32.bf16.bf16.f32 "
                 "{%0,%1,%2,%3},{%4,%5,%6,%7},{%8,%9},{%0,%1,%2,%3};"
                 : "+f"(c[0]), "+f"(c[1]), "+f"(c[2]), "+f"(c[3])
                 : "r"(a[0]), "r"(a[1]), "r"(a[2]), "r"(a[3]), "r"(b[0]), "r"(b[1]));
}
__device__ __forceinline__ void mma_tf32(float* c, const float* a, const float* b) {
    asm volatile("mma.sync.aligned.m16n8k8.row.col.f32.tf32.tf32.f32 "
                 "{%0,%1,%2,%3},{%4,%5,%6,%7},{%8,%9},{%0,%1,%2,%3};"
                 : "+f"(c[0]), "+f"(c[1]), "+f"(c[2]), "+f"(c[3])
                 : "r"(__float_as_uint(a[0])), "r"(__float_as_uint(a[1])),
                   "r"(__float_as_uint(a[2])), "r"(__float_as_uint(a[3])),
                   "r"(__float_as_uint(b[0])), "r"(__float_as_uint(b[1])));
}
__device__ __forceinline__ uint32_t f2bf2(float x, float y) {
    __nv_bfloat162 t = __floats2bfloat162_rn(x, y);
    return *reinterpret_cast<uint32_t*>(&t);
}
#define CP_ASYNC16(saddr, gptr) \
    asm volatile("cp.async.cg.shared.global [%0], [%1], 16;" :: "r"(saddr), "l"(gptr) : "memory")
#define CP_COMMIT() asm volatile("cp.async.commit_group;" ::: "memory")
#define CP_WAIT1()  asm volatile("cp.async.wait_group 1;" ::: "memory")
#define CP_WAIT0()  asm volatile("cp.async.wait_group 0;" ::: "memory")

// ---------------- prepass: relation fp32 -> bf16 (streaming hints) ------------
__global__ __launch_bounds__(256) void cvt_rel(const float* __restrict__ rel,
                                               __nv_bfloat16* __restrict__ dst)
{
    size_t i = ((size_t)blockIdx.x * 256 + threadIdx.x) * 8;
    float4 a = __ldcs((const float4*)(rel + i));
    float4 b = __ldcs((const float4*)(rel + i + 4));
    uint4 v = make_uint4(f2bf2(a.x, a.y), f2bf2(a.z, a.w),
                         f2bf2(b.x, b.y), f2bf2(b.z, b.w));
    __stcs((uint4*)((char*)dst + i * 2), v);
}

// ---------------- prepass: interleaved bf16 weight tiles [h][k][128] ----------
__global__ __launch_bounds__(256) void build_bw(const float* __restrict__ relw)
{
    int idx = blockIdx.x * 256 + threadIdx.x;    // 262144
    int d = idx & 63;
    int k = (idx >> 6) & 511;
    int h = idx >> 15;
    g_bw[((size_t)h*E_ + k) * 128 + 2*d    ] = __float2bfloat16(relw[(size_t)k*(2*E_) + h*64 + d]);
    g_bw[((size_t)h*E_ + k) * 128 + 2*d + 1] = __float2bfloat16(relw[(size_t)k*(2*E_) + E_ + h*64 + d]);
}

// ---------------- fused relation GEMM (bf16 HMMA, 3-stage, 2 CTAs/SM) ---------
#define RSA_STRIDE 16384
#define RSB_BASE   49152
#define RSB_STRIDE 16384
#define RELW_SMEM  98304
__global__ void __launch_bounds__(256, 2) relw_mma(const float* __restrict__ relb)
{
    extern __shared__ char smem[];
    const uint32_t AsBase = smem_u32(smem);
    const uint32_t BsBase = AsBase + RSB_BASE;
    float* red = (float*)smem;

    const int h   = blockIdx.x;
    const int n0  = blockIdx.y * 128;
    const int tid = threadIdx.x;
    const int lane = tid & 31, warp = tid >> 5;
    const int warp_m = warp >> 1, warp_n = warp & 1;

    float acc[2][8][4];
    #pragma unroll
    for (int i = 0; i < 2; i++)
        #pragma unroll
        for (int j = 0; j < 8; j++)
            #pragma unroll
            for (int k = 0; k < 4; k++) acc[i][j][k] = 0.f;

    const __nv_bfloat16* Ag = g_arel + (size_t)n0 * E_;
    const __nv_bfloat16* Bg = g_bw + (size_t)h * E_ * 128;

    auto load_stage = [&](int s, int buf) {
        uint32_t Ab = AsBase + buf * RSA_STRIDE;
        #pragma unroll
        for (int c = 0; c < 4; c++) {
            int idx = c * 256 + tid;
            int row = idx >> 3, cg = idx & 7;
            CP_ASYNC16(Ab + row*128 + (((cg ^ (row & 7)) << 4)),
                       Ag + (size_t)row * E_ + s*64 + cg*8);
        }
        uint32_t Bb = BsBase + buf * RSB_STRIDE;
        #pragma unroll
        for (int c = 0; c < 4; c++) {
            int idx = c * 256 + tid;
            int kr = idx >> 4, ng = idx & 15;
            CP_ASYNC16(Bb + kr*256 + (((ng ^ (kr & 7)) << 4)),
                       Bg + (size_t)(s*64 + kr) * 128 + ng*8);
        }
        CP_COMMIT();
    };

    load_stage(0, 0);
    load_stage(1, 1);

    const int a_r  = warp_m*32 + (lane & 15);
    const int a_kc = (lane >> 4) << 3;
    const int b_kr = lane & 15;
    const int b_nc = warp_n*64 + ((lane >> 4) << 3);

    #pragma unroll
    for (int s = 0; s < 8; s++) {
        if (s < 7) CP_WAIT1(); else CP_WAIT0();
        __syncthreads();
        if (s < 6) load_stage(s + 2, (s + 2) % 3);

        const uint32_t Ab = AsBase + (s % 3) * RSA_STRIDE;
        const uint32_t Bb = BsBase + (s % 3) * RSB_STRIDE;

        #pragma unroll
        for (int ks = 0; ks < 4; ks++) {
            uint32_t a[2][4];
            #pragma unroll
            for (int mi = 0; mi < 2; mi++) {
                int r  = a_r + mi*16;
                int kc = a_kc + ks*16;
                ldsm_x4(a[mi][0], a[mi][1], a[mi][2], a[mi][3],
                        Ab + r*128 + ((((kc >> 3) ^ (r & 7)) << 4)));
            }
            uint32_t b[8][2];
            #pragma unroll
            for (int g = 0; g < 4; g++) {
                int krow = b_kr + ks*16;
                int ncol = b_nc + g*16;
                ldsm_x4_t(b[2*g][0], b[2*g][1], b[2*g+1][0], b[2*g+1][1],
                          Bb + krow*256 + ((((ncol >> 3) ^ (krow & 7)) << 4)));
            }
            #pragma unroll
            for (int mi = 0; mi < 2; mi++)
                #pragma unroll
                for (int nf = 0; nf < 8; nf++)
                    mma16816(acc[mi][nf], a[mi], b[nf]);
        }
    }

    // ---- fused epilogue --------------------------------------------------------
    const int tig = lane & 3, grp = lane >> 2;
    float part[2][2] = {{0.f, 0.f}, {0.f, 0.f}};
    #pragma unroll
    for (int nf = 0; nf < 8; nf++) {
        int d = warp_n*32 + nf*4 + tig;
        float bra = relb[h*64 + d];
        float brb = relb[E_ + h*64 + d];
        #pragma unroll
        for (int mi = 0; mi < 2; mi++)
            #pragma unroll
            for (int hf = 0; hf < 2; hf++) {
                int r  = warp_m*32 + mi*16 + grp + hf*8;
                int n  = n0 + r;
                int b  = n & 31;
                int ji = n >> 5;
                int ii = ji & 63, jj = ji >> 6;
                float q = g_qkv[(size_t)(ii*B_ + b) * (3*E_) + h*64 + d];
                float k = g_qkv[(size_t)(jj*B_ + b) * (3*E_) + E_ + h*64 + d];
                part[mi][hf] += (acc[mi][nf][hf*2+0] + bra + q) * (acc[mi][nf][hf*2+1] + brb + k);
            }
    }
    #pragma unroll
    for (int mi = 0; mi < 2; mi++)
        #pragma unroll
        for (int hf = 0; hf < 2; hf++) {
            float v = part[mi][hf];
            v += __shfl_xor_sync(~0u, v, 1);
            v += __shfl_xor_sync(~0u, v, 2);
            part[mi][hf] = v;
        }
    __syncthreads();
    if (tig == 0) {
        #pragma unroll
        for (int mi = 0; mi < 2; mi++)
            #pragma unroll
            for (int hf = 0; hf < 2; hf++) {
                int r = warp_m*32 + mi*16 + grp + hf*8;
                red[r*2 + warp_n] = part[mi][hf];
            }
    }
    __syncthreads();
    if (tid < 128) {
        int n  = n0 + tid;
        int b  = n & 31;
        int ji = n >> 5;
        int ii = ji & 63, jj = ji >> 6;
        g_w[((size_t)(ii*B_ + b) * H_ + h) * T_ + jj] =
            (red[tid*2] + red[tid*2 + 1]) * 0.015625f;
    }
}

// ---------------- tf32 GEMM, cp.async 3-stage, 2 CTAs/SM ----------------------
#define GPA 36
#define GPB 136
template<int MI, bool BTRANS, int EPI>
__global__ __launch_bounds__(256, 2) void gemm_tf32(
    const float* __restrict__ A, const float* __restrict__ Bm,
    const float* __restrict__ bias, const float* __restrict__ add,
    float* __restrict__ C, int M, int N, int K)
{
    constexpr int MT = 64 * MI;
    constexpr int AW = MT * GPA;
    constexpr int BW = BTRANS ? 128 * GPA : 32 * GPB;
    extern __shared__ float sm[];
    const uint32_t smemb = smem_u32(sm);
    const uint32_t AsU = smemb;
    const uint32_t BsU = smemb + 3 * AW * 4;

    const int tid = threadIdx.x;
    const int lane = tid & 31, warp = tid >> 5;
    const int wm = warp >> 1, wn = warp & 1;
    const int grp = lane >> 2, tig = lane & 3;
    const int m0 = blockIdx.y * MT;
    const int n0 = blockIdx.x * 128;

    float acc[MI][8][4];
    #pragma unroll
    for (int i = 0; i < MI; i++)
        #pragma unroll
        for (int j = 0; j < 8; j++)
            #pragma unroll
            for (int k = 0; k < 4; k++) acc[i][j][k] = 0.f;

    const int S = K >> 5;

    auto load_stage = [&](int s, int buf) {
        uint32_t Ab = AsU + buf * AW * 4;
        #pragma unroll
        for (int c = 0; c < 2*MI; c++) {
            int idx = c * 256 + tid;
            int row = idx >> 3, cg = idx & 7;
            CP_ASYNC16(Ab + row*(GPA*4) + cg*16,
                       A + (size_t)(m0 + row) * K + s*32 + cg*4);
        }
        uint32_t Bb = BsU + buf * BW * 4;
        #pragma unroll
        for (int c = 0; c < 4; c++) {
            int idx = c * 256 + tid;
            if (BTRANS) {
                int nr = idx >> 3, cg = idx & 7;
                CP_ASYNC16(Bb + nr*(GPA*4) + cg*16,
                           Bm + (size_t)(n0 + nr) * K + s*32 + cg*4);
            } else {
                int kr = idx >> 5, ng = idx & 31;
                CP_ASYNC16(Bb + kr*(GPB*4) + ng*16,
                           Bm + (size_t)(s*32 + kr) * N + n0 + ng*4);
            }
        }
        CP_COMMIT();
    };

    load_stage(0, 0);
    load_stage(1, 1);

    for (int s = 0; s < S; s++) {
        if (s < S - 1) CP_WAIT1(); else CP_WAIT0();
        __syncthreads();
        if (s < S - 2) load_stage(s + 2, (s + 2) % 3);

        const float* Ab = sm + (s % 3) * AW;
        const float* Bb = sm + 3 * AW + (s % 3) * BW;
        #pragma unroll
        for (int ks = 0; ks < 4; ks++) {
            float a[MI][4];
            #pragma unroll
            for (int mi = 0; mi < MI; mi++) {
                int r = wm*(16*MI) + mi*16 + grp;
                int c = ks*8 + tig;
                a[mi][0] = Ab[r * GPA + c];
                a[mi][1] = Ab[(r + 8) * GPA + c];
                a[mi][2] = Ab[r * GPA + c + 4];
                a[mi][3] = Ab[(r + 8) * GPA + c + 4];
            }
            float b[8][2];
            #pragma unroll
            for (int nf = 0; nf < 8; nf++) {
                int n = wn*64 + nf*8 + grp;
                if (BTRANS) {
                    b[nf][0] = Bb[n * GPA + ks*8 + tig];
                    b[nf][1] = Bb[n * GPA + ks*8 + tig + 4];
                } else {
                    b[nf][0] = Bb[(ks*8 + tig) * GPB + n];
                    b[nf][1] = Bb[(ks*8 + tig + 4) * GPB + n];
                }
            }
            #pragma unroll
            for (int mi = 0; mi < MI; mi++)
                #pragma unroll
                for (int nf = 0; nf < 8; nf++)
                    mma_tf32(acc[mi][nf], a[mi], b[nf]);
        }
    }

    #pragma unroll
    for (int mi = 0; mi < MI; mi++)
        #pragma unroll
        for (int hf = 0; hf < 2; hf++) {
            int row = m0 + wm*(16*MI) + mi*16 + grp + hf*8;
            #pragma unroll
            for (int nf = 0; nf < 8; nf++) {
                int col = n0 + wn*64 + nf*8 + tig*2;
                float v0 = acc[mi][nf][hf*2 + 0] + bias[col];
                float v1 = acc[mi][nf][hf*2 + 1] + bias[col + 1];
                if (EPI == 1) { v0 = fmaxf(v0, 0.f); v1 = fmaxf(v1, 0.f); }
                if (EPI == 2) {
                    v0 += add[(size_t)row * N + col];
                    v1 += add[(size_t)row * N + col + 1];
                }
                *(float2*)(C + (size_t)row * N + col) = make_float2(v0, v1);
            }
        }
}

// ---------------- softmax + attn, one CTA per (b, h) --------------------------
__global__ __launch_bounds__(256) void softmax_attn_kernel()
{
    const int b = blockIdx.x, h = blockIdx.y;
    __shared__ float p[64][68];
    __shared__ float vs[64][68];
    const int t = threadIdx.x;
    const int i = t >> 2, q = t & 3;
    const int d0 = q * 16;

    {
        const float* src = g_qkv + (size_t)(i*B_ + b)*(3*E_) + 2*E_ + h*64 + d0;
        #pragma unroll
        for (int e = 0; e < 16; e += 4)
            *(float4*)&vs[i][d0 + e] = *(const float4*)(src + e);
    }
    {
        float w[16];
        const float* wr = g_w + ((size_t)(i*B_ + b)*H_ + h)*T_ + d0;
        #pragma unroll
        for (int e = 0; e < 16; e += 4) {
            float4 v4 = *(const float4*)(wr + e);
            w[e] = v4.x; w[e+1] = v4.y; w[e+2] = v4.z; w[e+3] = v4.w;
        }
        float mx = w[0];
        #pragma unroll
        for (int e = 1; e < 16; e++) mx = fmaxf(mx, w[e]);
        mx = fmaxf(mx, __shfl_xor_sync(~0u, mx, 1));
        mx = fmaxf(mx, __shfl_xor_sync(~0u, mx, 2));
        float s = 0.f;
        #pragma unroll
        for (int e = 0; e < 16; e++) { w[e] = expf(w[e] - mx); s += w[e]; }
        s += __shfl_xor_sync(~0u, s, 1);
        s += __shfl_xor_sync(~0u, s, 2);
        float inv = 1.f / s;
        #pragma unroll
        for (int e = 0; e < 16; e++) p[i][d0 + e] = w[e] * inv;
    }
    __syncthreads();

    float acc[16] = {};
    for (int j = 0; j < 64; j++) {
        float pij = p[i][j];
        #pragma unroll
        for (int e = 0; e < 16; e += 4) {
            float4 v4 = *(float4*)&vs[j][d0 + e];
            acc[e]   = fmaf(pij, v4.x, acc[e]);
            acc[e+1] = fmaf(pij, v4.y, acc[e+1]);
            acc[e+2] = fmaf(pij, v4.z, acc[e+2]);
            acc[e+3] = fmaf(pij, v4.w, acc[e+3]);
        }
    }
    float* dst = g_attn + (size_t)(i*B_ + b)*E_ + h*64 + d0;
    #pragma unroll
    for (int e = 0; e < 16; e += 4)
        *(float4*)(dst + e) = make_float4(acc[e], acc[e+1], acc[e+2], acc[e+3]);
}

// ---------------- layernorm ----------------------------------------------------
__global__ __launch_bounds__(256) void ln_kernel(
    const float* __restrict__ in, const float* __restrict__ g,
    const float* __restrict__ b, float* __restrict__ out)
{
    int row = blockIdx.x;
    const float* r = in + (size_t)row * E_;
    int t = threadIdx.x;
    float v0 = r[t], v1 = r[t + 256];
    float s = v0 + v1, sq = v0*v0 + v1*v1;
    #pragma unroll
    for (int o = 16; o; o >>= 1) {
        s  += __shfl_xor_sync(~0u, s,  o);
        sq += __shfl_xor_sync(~0u, sq, o);
    }
    __shared__ float ss[8], ssq[8];
    int w = t >> 5, l = t & 31;
    if (l == 0) { ss[w] = s; ssq[w] = sq; }
    __syncthreads();
    if (w == 0) {
        s  = (l < 8) ? ss[l]  : 0.f;
        sq = (l < 8) ? ssq[l] : 0.f;
        #pragma unroll
        for (int o = 4; o; o >>= 1) {
            s  += __shfl_xor_sync(~0u, s,  o);
            sq += __shfl_xor_sync(~0u, sq, o);
        }
        if (l == 0) { ss[0] = s; ssq[0] = sq; }
    }
    __syncthreads();
    float mu   = ss[0]  * (1.f / E_);
    float var  = ssq[0] * (1.f / E_) - mu * mu;
    float rstd = rsqrtf(var + 1e-5f);
    out[(size_t)row*E_ + t]       = (v0 - mu) * rstd * g[t]       + b[t];
    out[(size_t)row*E_ + t + 256] = (v1 - mu) * rstd * g[t + 256] + b[t + 256];
}

// ---------------- launch --------------------------------------------------------
extern "C" void kernel_launch(void* const* d_in, const int* in_sizes, int n_in,
                              void* d_out, int out_size)
{
    const float* x        = (const float*)d_in[0];
    const float* relation = (const float*)d_in[1];
    const float* in_w     = (const float*)d_in[2];
    const float* in_b     = (const float*)d_in[3];
    const float* rel_w    = (const float*)d_in[4];
    const float* rel_b    = (const float*)d_in[5];
    const float* out_w    = (const float*)d_in[6];
    const float* out_b    = (const float*)d_in[7];
    const float* fc1_w    = (const float*)d_in[8];
    const float* fc1_b    = (const float*)d_in[9];
    const float* fc2_w    = (const float*)d_in[10];
    const float* fc2_b    = (const float*)d_in[11];
    const float* ln1_g    = (const float*)d_in[12];
    const float* ln1_b    = (const float*)d_in[13];
    const float* ln2_g    = (const float*)d_in[14];
    const float* ln2_b    = (const float*)d_in[15];
    float* out = (float*)d_out;

    const int SM_BT128 = 3 * (128*GPA + 128*GPA) * 4;   // qkv MI=2 (110592)
    const int SM_BN64  = 3 * (64*GPA  + 32*GPB) * 4;    // out/fc2 MI=1
    const int SM_BN128 = 3 * (128*GPA + 32*GPB) * 4;    // fc1 MI=2

    static float *p_qkv = nullptr, *p_attn, *p_ao, *p_h, *p_f1, *p_f2;
    static __nv_bfloat16* p_arel;
    static cudaStream_t s_side;
    static cudaEvent_t ev_fork, ev_join;
    if (!p_qkv) {
        cudaGetSymbolAddress((void**)&p_qkv,  g_qkv);
        cudaGetSymbolAddress((void**)&p_attn, g_attn);
        cudaGetSymbolAddress((void**)&p_ao,   g_ao);
        cudaGetSymbolAddress((void**)&p_h,    g_h);
        cudaGetSymbolAddress((void**)&p_f1,   g_f1);
        cudaGetSymbolAddress((void**)&p_f2,   g_f2);
        cudaGetSymbolAddress((void**)&p_arel, g_arel);
        cudaFuncSetAttribute(relw_mma, cudaFuncAttributeMaxDynamicSharedMemorySize, RELW_SMEM);
        cudaFuncSetAttribute(gemm_tf32<2, true, 0>,  cudaFuncAttributeMaxDynamicSharedMemorySize, SM_BT128);
        cudaFuncSetAttribute(gemm_tf32<1, false, 2>, cudaFuncAttributeMaxDynamicSharedMemorySize, SM_BN64);
        cudaFuncSetAttribute(gemm_tf32<2, false, 1>, cudaFuncAttributeMaxDynamicSharedMemorySize, SM_BN128);
        cudaStreamCreateWithFlags(&s_side, cudaStreamNonBlocking);
        cudaEventCreateWithFlags(&ev_fork, cudaEventDisableTiming);
        cudaEventCreateWithFlags(&ev_join, cudaEventDisableTiming);
    }

    dim3 blk(256);

    // ---- fork: cvt_rel on side stream (overlaps bw + qkv only) -----------------
    cudaEventRecord(ev_fork, 0);
    cudaStreamWaitEvent(s_side, ev_fork, 0);
    cvt_rel<<<ROWS_ * E_ / (8 * 256), 256, 0, s_side>>>(relation, p_arel);
    cudaEventRecord(ev_join, s_side);

    build_bw<<<1024, 256>>>(rel_w);
    // 1. qkv (tf32, MI=2: grid 192 = single wave)
    gemm_tf32<2, true, 0><<<dim3(1536/128, TB_/128), blk, SM_BT128>>>(x, in_w, in_b, nullptr, p_qkv, TB_, 3*E_, E_);

    cudaStreamWaitEvent(0, ev_join, 0);

    // 2. relation GEMM (bf16 HMMA) + fused logits
    relw_mma<<<dim3(H_, ROWS_/128), blk, RELW_SMEM>>>(rel_b);

    // 3. softmax + attn, CTA per (b,h)
    softmax_attn_kernel<<<dim3(B_, H_), 256>>>();

    // 4. out proj + residual  (MI=1)
    gemm_tf32<1, false, 2><<<dim3(E_/128, TB_/64), blk, SM_BN64>>>(p_attn, out_w, out_b, x, p_ao, TB_, E_, E_);

    // 5. LN1
    ln_kernel<<<TB_, 256>>>(p_ao, ln1_g, ln1_b, p_h);

    // 6. fc1 + relu  (MI=2)
    gemm_tf32<2, false, 1><<<dim3(F_/128, TB_/128), blk, SM_BN128>>>(p_h, fc1_w, fc1_b, nullptr, p_f1, TB_, F_, E_);

    // 7. fc2 + residual h  (MI=1)
    gemm_tf32<1, false, 2><<<dim3(E_/128, TB_/64), blk, SM_BN64>>>(p_f1, fc2_w, fc2_b, p_h, p_f2, TB_, E_, F_);

    // 8. LN2 -> out
    ln_kernel<<<TB_, 256>>>(p_f2, ln2_g, ln2_b, out);
}

// round 15
// speedup vs baseline: 1.0824x; 1.0472x over previous
#include <cuda_runtime.h>
#include <cuda_bf16.h>
#include <cuda_fp16.h>
#include <cstdint>

#define T_  64
#define B_  32
#define E_  512
#define H_  8
#define F_  2048
#define TB_ (T_*B_)        // 2048
#define ROWS_ (T_*T_*B_)   // 131072

// ---------------- scratch ----------------------------------------------------
__device__ float g_qkv[TB_ * 3 * E_];
__device__ float g_w[TB_ * H_ * T_];
__device__ float g_attn[TB_ * E_];
__device__ float g_ao[TB_ * E_];
__device__ float g_h[TB_ * E_];
__device__ float g_f2[TB_ * E_];
__device__ __nv_bfloat16 g_arel[(size_t)ROWS_ * E_];   // relation in bf16 (134MB)
__device__ __nv_bfloat16 g_bw[H_ * E_ * 128];          // [h][k][2d interleaved ra/rb]
__device__ __half g_hh[TB_ * E_];                      // h in fp16 (fc1 A)
__device__ __half g_f1h[TB_ * F_];                     // relu(fc1) in fp16 (fc2 A)
__device__ __half g_w1h[E_ * F_];                      // fc1_w fp16
__device__ __half g_w2h[F_ * E_];                      // fc2_w fp16

// ---------------- helpers ------------------------------------------------------
__device__ __forceinline__ uint32_t smem_u32(const void* p) {
    return (uint32_t)__cvta_generic_to_shared(p);
}
__device__ __forceinline__ void ldsm_x4(uint32_t& r0, uint32_t& r1, uint32_t& r2, uint32_t& r3, uint32_t a) {
    asm volatile("ldmatrix.sync.aligned.m8n8.x4.shared.b16 {%0,%1,%2,%3},[%4];"
                 : "=r"(r0), "=r"(r1), "=r"(r2), "=r"(r3) : "r"(a));
}
__device__ __forceinline__ void ldsm_x4_t(uint32_t& r0, uint32_t& r1, uint32_t& r2, uint32_t& r3, uint32_t a) {
    asm volatile("ldmatrix.sync.aligned.m8n8.x4.trans.shared.b16 {%0,%1,%2,%3},[%4];"
                 : "=r"(r0), "=r"(r1), "=r"(r2), "=r"(r3) : "r"(a));
}
__device__ __forceinline__ void mma16816(float* c, const uint32_t* a, const uint32_t* b) {
    asm volatile("mma.sync.aligned.m16n8k16.row.col.f32.bf16.bf16.f32 "
                 "{%0,%1,%2,%3},{%4,%5,%6,%7},{%8,%9},{%0,%1,%2,%3};"
                 : "+f"(c[0]), "+f"(c[1]), "+f"(c[2]), "+f"(c[3])
                 : "r"(a[0]), "r"(a[1]), "r"(a[2]), "r"(a[3]), "r"(b[0]), "r"(b[1]));
}
__device__ __forceinline__ void mma16816h(float* c, const uint32_t* a, const uint32_t* b) {
    asm volatile("mma.sync.aligned.m16n8k16.row.col.f32.f16.f16.f32 "
                 "{%0,%1,%2,%3},{%4,%5,%6,%7},{%8,%9},{%0,%1,%2,%3};"
                 : "+f"(c[0]), "+f"(c[1]), "+f"(c[2]), "+f"(c[3])
                 : "r"(a[0]), "r"(a[1]), "r"(a[2]), "r"(a[3]), "r"(b[0]), "r"(b[1]));
}
__device__ __forceinline__ void mma_tf32(float* c, const float* a, const float* b) {
    asm volatile("mma.sync.aligned.m16n8k8.row.col.f32.tf32.tf32.f32 "
                 "{%0,%1,%2,%3},{%4,%5,%6,%7},{%8,%9},{%0,%1,%2,%3};"
                 : "+f"(c[0]), "+f"(c[1]), "+f"(c[2]), "+f"(c[3])
                 : "r"(__float_as_uint(a[0])), "r"(__float_as_uint(a[1])),
                   "r"(__float_as_uint(a[2])), "r"(__float_as_uint(a[3])),
                   "r"(__float_as_uint(b[0])), "r"(__float_as_uint(b[1])));
}
__device__ __forceinline__ uint32_t f2bf2(float x, float y) {
    __nv_bfloat162 t = __floats2bfloat162_rn(x, y);
    return *reinterpret_cast<uint32_t*>(&t);
}
__device__ __forceinline__ uint32_t f2h2(float x, float y) {
    __half2 t = __floats2half2_rn(x, y);
    return *reinterpret_cast<uint32_t*>(&t);
}
#define CP_ASYNC16(saddr, gptr) \
    asm volatile("cp.async.cg.shared.global [%0], [%1], 16;" :: "r"(saddr), "l"(gptr) : "memory")
#define CP_COMMIT() asm volatile("cp.async.commit_group;" ::: "memory")
#define CP_WAIT1()  asm volatile("cp.async.wait_group 1;" ::: "memory")
#define CP_WAIT0()  asm volatile("cp.async.wait_group 0;" ::: "memory")

// ---------------- prepass: relation fp32 -> bf16 (streaming hints) ------------
__global__ __launch_bounds__(256) void cvt_rel(const float* __restrict__ rel,
                                               __nv_bfloat16* __restrict__ dst)
{
    size_t i = ((size_t)blockIdx.x * 256 + threadIdx.x) * 8;
    float4 a = __ldcs((const float4*)(rel + i));
    float4 b = __ldcs((const float4*)(rel + i + 4));
    uint4 v = make_uint4(f2bf2(a.x, a.y), f2bf2(a.z, a.w),
                         f2bf2(b.x, b.y), f2bf2(b.z, b.w));
    __stcs((uint4*)((char*)dst + i * 2), v);
}

// ---------------- prepass: fp32 -> fp16 (weights) ------------------------------
__global__ __launch_bounds__(256) void cvt_f16(const float* __restrict__ src,
                                               __half* __restrict__ dst)
{
    size_t i = ((size_t)blockIdx.x * 256 + threadIdx.x) * 8;
    float4 a = *(const float4*)(src + i);
    float4 b = *(const float4*)(src + i + 4);
    uint4 v = make_uint4(f2h2(a.x, a.y), f2h2(a.z, a.w),
                         f2h2(b.x, b.y), f2h2(b.z, b.w));
    *(uint4*)((char*)dst + i * 2) = v;
}

// ---------------- prepass: interleaved bf16 weight tiles [h][k][128] ----------
__global__ __launch_bounds__(256) void build_bw(const float* __restrict__ relw)
{
    int idx = blockIdx.x * 256 + threadIdx.x;    // 262144
    int d = idx & 63;
    int k = (idx >> 6) & 511;
    int h = idx >> 15;
    g_bw[((size_t)h*E_ + k) * 128 + 2*d    ] = __float2bfloat16(relw[(size_t)k*(2*E_) + h*64 + d]);
    g_bw[((size_t)h*E_ + k) * 128 + 2*d + 1] = __float2bfloat16(relw[(size_t)k*(2*E_) + E_ + h*64 + d]);
}

// ---------------- fused relation GEMM (bf16 HMMA, 3-stage, 2 CTAs/SM) ---------
#define RSA_STRIDE 16384
#define RSB_BASE   49152
#define RSB_STRIDE 16384
#define RELW_SMEM  98304
__global__ void __launch_bounds__(256, 2) relw_mma(const float* __restrict__ relb)
{
    extern __shared__ char smem[];
    const uint32_t AsBase = smem_u32(smem);
    const uint32_t BsBase = AsBase + RSB_BASE;
    float* red = (float*)smem;

    const int h   = blockIdx.x;
    const int n0  = blockIdx.y * 128;
    const int tid = threadIdx.x;
    const int lane = tid & 31, warp = tid >> 5;
    const int warp_m = warp >> 1, warp_n = warp & 1;

    float acc[2][8][4];
    #pragma unroll
    for (int i = 0; i < 2; i++)
        #pragma unroll
        for (int j = 0; j < 8; j++)
            #pragma unroll
            for (int k = 0; k < 4; k++) acc[i][j][k] = 0.f;

    const __nv_bfloat16* Ag = g_arel + (size_t)n0 * E_;
    const __nv_bfloat16* Bg = g_bw + (size_t)h * E_ * 128;

    auto load_stage = [&](int s, int buf) {
        uint32_t Ab = AsBase + buf * RSA_STRIDE;
        #pragma unroll
        for (int c = 0; c < 4; c++) {
            int idx = c * 256 + tid;
            int row = idx >> 3, cg = idx & 7;
            CP_ASYNC16(Ab + row*128 + (((cg ^ (row & 7)) << 4)),
                       Ag + (size_t)row * E_ + s*64 + cg*8);
        }
        uint32_t Bb = BsBase + buf * RSB_STRIDE;
        #pragma unroll
        for (int c = 0; c < 4; c++) {
            int idx = c * 256 + tid;
            int kr = idx >> 4, ng = idx & 15;
            CP_ASYNC16(Bb + kr*256 + (((ng ^ (kr & 7)) << 4)),
                       Bg + (size_t)(s*64 + kr) * 128 + ng*8);
        }
        CP_COMMIT();
    };

    load_stage(0, 0);
    load_stage(1, 1);

    const int a_r  = warp_m*32 + (lane & 15);
    const int a_kc = (lane >> 4) << 3;
    const int b_kr = lane & 15;
    const int b_nc = warp_n*64 + ((lane >> 4) << 3);

    #pragma unroll
    for (int s = 0; s < 8; s++) {
        if (s < 7) CP_WAIT1(); else CP_WAIT0();
        __syncthreads();
        if (s < 6) load_stage(s + 2, (s + 2) % 3);

        const uint32_t Ab = AsBase + (s % 3) * RSA_STRIDE;
        const uint32_t Bb = BsBase + (s % 3) * RSB_STRIDE;

        #pragma unroll
        for (int ks = 0; ks < 4; ks++) {
            uint32_t a[2][4];
            #pragma unroll
            for (int mi = 0; mi < 2; mi++) {
                int r  = a_r + mi*16;
                int kc = a_kc + ks*16;
                ldsm_x4(a[mi][0], a[mi][1], a[mi][2], a[mi][3],
                        Ab + r*128 + ((((kc >> 3) ^ (r & 7)) << 4)));
            }
            uint32_t b[8][2];
            #pragma unroll
            for (int g = 0; g < 4; g++) {
                int krow = b_kr + ks*16;
                int ncol = b_nc + g*16;
                ldsm_x4_t(b[2*g][0], b[2*g][1], b[2*g+1][0], b[2*g+1][1],
                          Bb + krow*256 + ((((ncol >> 3) ^ (krow & 7)) << 4)));
            }
            #pragma unroll
            for (int mi = 0; mi < 2; mi++)
                #pragma unroll
                for (int nf = 0; nf < 8; nf++)
                    mma16816(acc[mi][nf], a[mi], b[nf]);
        }
    }

    // ---- fused epilogue --------------------------------------------------------
    const int tig = lane & 3, grp = lane >> 2;
    float part[2][2] = {{0.f, 0.f}, {0.f, 0.f}};
    #pragma unroll
    for (int nf = 0; nf < 8; nf++) {
        int d = warp_n*32 + nf*4 + tig;
        float bra = relb[h*64 + d];
        float brb = relb[E_ + h*64 + d];
        #pragma unroll
        for (int mi = 0; mi < 2; mi++)
            #pragma unroll
            for (int hf = 0; hf < 2; hf++) {
                int r  = warp_m*32 + mi*16 + grp + hf*8;
                int n  = n0 + r;
                int b  = n & 31;
                int ji = n >> 5;
                int ii = ji & 63, jj = ji >> 6;
                float q = g_qkv[(size_t)(ii*B_ + b) * (3*E_) + h*64 + d];
                float k = g_qkv[(size_t)(jj*B_ + b) * (3*E_) + E_ + h*64 + d];
                part[mi][hf] += (acc[mi][nf][hf*2+0] + bra + q) * (acc[mi][nf][hf*2+1] + brb + k);
            }
    }
    #pragma unroll
    for (int mi = 0; mi < 2; mi++)
        #pragma unroll
        for (int hf = 0; hf < 2; hf++) {
            float v = part[mi][hf];
            v += __shfl_xor_sync(~0u, v, 1);
            v += __shfl_xor_sync(~0u, v, 2);
            part[mi][hf] = v;
        }
    __syncthreads();
    if (tig == 0) {
        #pragma unroll
        for (int mi = 0; mi < 2; mi++)
            #pragma unroll
            for (int hf = 0; hf < 2; hf++) {
                int r = warp_m*32 + mi*16 + grp + hf*8;
                red[r*2 + warp_n] = part[mi][hf];
            }
    }
    __syncthreads();
    if (tid < 128) {
        int n  = n0 + tid;
        int b  = n & 31;
        int ji = n >> 5;
        int ii = ji & 63, jj = ji >> 6;
        g_w[((size_t)(ii*B_ + b) * H_ + h) * T_ + jj] =
            (red[tid*2] + red[tid*2 + 1]) * 0.015625f;
    }
}

// ---------------- fp16 GEMM: 128x128 tile, K-stage 64, 3-stage, 2 CTAs/SM -----
// A [M,K] half row-major, B [K,N] half row-major.
// EPI 1: relu, write half (C = __half*). EPI 2: +add (fp32), write float.
template<int EPI>
__global__ void __launch_bounds__(256, 2) gemm_h16(
    const __half* __restrict__ A, const __half* __restrict__ Bm,
    const float* __restrict__ bias, const float* __restrict__ add,
    void* __restrict__ Cv, int M, int N, int K)
{
    extern __shared__ char smem[];
    const uint32_t AsBase = smem_u32(smem);
    const uint32_t BsBase = AsBase + RSB_BASE;

    const int tid = threadIdx.x;
    const int lane = tid & 31, warp = tid >> 5;
    const int warp_m = warp >> 1, warp_n = warp & 1;
    const int m0 = blockIdx.y * 128;
    const int n0 = blockIdx.x * 128;

    float acc[2][8][4];
    #pragma unroll
    for (int i = 0; i < 2; i++)
        #pragma unroll
        for (int j = 0; j < 8; j++)
            #pragma unroll
            for (int k = 0; k < 4; k++) acc[i][j][k] = 0.f;

    const __half* Ag = A + (size_t)m0 * K;
    const int S = K >> 6;

    auto load_stage = [&](int s, int buf) {
        uint32_t Ab = AsBase + buf * RSA_STRIDE;
        #pragma unroll
        for (int c = 0; c < 4; c++) {
            int idx = c * 256 + tid;
            int row = idx >> 3, cg = idx & 7;
            CP_ASYNC16(Ab + row*128 + (((cg ^ (row & 7)) << 4)),
                       Ag + (size_t)row * K + s*64 + cg*8);
        }
        uint32_t Bb = BsBase + buf * RSB_STRIDE;
        #pragma unroll
        for (int c = 0; c < 4; c++) {
            int idx = c * 256 + tid;
            int kr = idx >> 4, ng = idx & 15;
            CP_ASYNC16(Bb + kr*256 + (((ng ^ (kr & 7)) << 4)),
                       Bm + (size_t)(s*64 + kr) * N + n0 + ng*8);
        }
        CP_COMMIT();
    };

    load_stage(0, 0);
    load_stage(1, 1);

    const int a_r  = warp_m*32 + (lane & 15);
    const int a_kc = (lane >> 4) << 3;
    const int b_kr = lane & 15;
    const int b_nc = warp_n*64 + ((lane >> 4) << 3);

    for (int s = 0; s < S; s++) {
        if (s < S - 1) CP_WAIT1(); else CP_WAIT0();
        __syncthreads();
        if (s < S - 2) load_stage(s + 2, (s + 2) % 3);

        const uint32_t Ab = AsBase + (s % 3) * RSA_STRIDE;
        const uint32_t Bb = BsBase + (s % 3) * RSB_STRIDE;

        #pragma unroll
        for (int ks = 0; ks < 4; ks++) {
            uint32_t a[2][4];
            #pragma unroll
            for (int mi = 0; mi < 2; mi++) {
                int r  = a_r + mi*16;
                int kc = a_kc + ks*16;
                ldsm_x4(a[mi][0], a[mi][1], a[mi][2], a[mi][3],
                        Ab + r*128 + ((((kc >> 3) ^ (r & 7)) << 4)));
            }
            uint32_t b[8][2];
            #pragma unroll
            for (int g = 0; g < 4; g++) {
                int krow = b_kr + ks*16;
                int ncol = b_nc + g*16;
                ldsm_x4_t(b[2*g][0], b[2*g][1], b[2*g+1][0], b[2*g+1][1],
                          Bb + krow*256 + ((((ncol >> 3) ^ (krow & 7)) << 4)));
            }
            #pragma unroll
            for (int mi = 0; mi < 2; mi++)
                #pragma unroll
                for (int nf = 0; nf < 8; nf++)
                    mma16816h(acc[mi][nf], a[mi], b[nf]);
        }
    }

    // ---- epilogue ---------------------------------------------------------------
    const int tig = lane & 3, grp = lane >> 2;
    #pragma unroll
    for (int mi = 0; mi < 2; mi++)
        #pragma unroll
        for (int hf = 0; hf < 2; hf++) {
            int row = m0 + warp_m*32 + mi*16 + grp + hf*8;
            #pragma unroll
            for (int nf = 0; nf < 8; nf++) {
                int col = n0 + warp_n*64 + nf*8 + tig*2;
                float v0 = acc[mi][nf][hf*2 + 0] + bias[col];
                float v1 = acc[mi][nf][hf*2 + 1] + bias[col + 1];
                if (EPI == 1) {
                    v0 = fmaxf(v0, 0.f); v1 = fmaxf(v1, 0.f);
                    *(uint32_t*)((__half*)Cv + (size_t)row * N + col) = f2h2(v0, v1);
                } else {
                    v0 += add[(size_t)row * N + col];
                    v1 += add[(size_t)row * N + col + 1];
                    *(float2*)((float*)Cv + (size_t)row * N + col) = make_float2(v0, v1);
                }
            }
        }
}

// ---------------- tf32 GEMM, cp.async 3-stage, 2 CTAs/SM ----------------------
#define GPA 36
#define GPB 136
template<int MI, bool BTRANS, int EPI>
__global__ __launch_bounds__(256, 2) void gemm_tf32(
    const float* __restrict__ A, const float* __restrict__ Bm,
    const float* __restrict__ bias, const float* __restrict__ add,
    float* __restrict__ C, int M, int N, int K)
{
    constexpr int MT = 64 * MI;
    constexpr int AW = MT * GPA;
    constexpr int BW = BTRANS ? 128 * GPA : 32 * GPB;
    extern __shared__ float sm[];
    const uint32_t smemb = smem_u32(sm);
    const uint32_t AsU = smemb;
    const uint32_t BsU = smemb + 3 * AW * 4;

    const int tid = threadIdx.x;
    const int lane = tid & 31, warp = tid >> 5;
    const int wm = warp >> 1, wn = warp & 1;
    const int grp = lane >> 2, tig = lane & 3;
    const int m0 = blockIdx.y * MT;
    const int n0 = blockIdx.x * 128;

    float acc[MI][8][4];
    #pragma unroll
    for (int i = 0; i < MI; i++)
        #pragma unroll
        for (int j = 0; j < 8; j++)
            #pragma unroll
            for (int k = 0; k < 4; k++) acc[i][j][k] = 0.f;

    const int S = K >> 5;

    auto load_stage = [&](int s, int buf) {
        uint32_t Ab = AsU + buf * AW * 4;
        #pragma unroll
        for (int c = 0; c < 2*MI; c++) {
            int idx = c * 256 + tid;
            int row = idx >> 3, cg = idx & 7;
            CP_ASYNC16(Ab + row*(GPA*4) + cg*16,
                       A + (size_t)(m0 + row) * K + s*32 + cg*4);
        }
        uint32_t Bb = BsU + buf * BW * 4;
        #pragma unroll
        for (int c = 0; c < 4; c++) {
            int idx = c * 256 + tid;
            if (BTRANS) {
                int nr = idx >> 3, cg = idx & 7;
                CP_ASYNC16(Bb + nr*(GPA*4) + cg*16,
                           Bm + (size_t)(n0 + nr) * K + s*32 + cg*4);
            } else {
                int kr = idx >> 5, ng = idx & 31;
                CP_ASYNC16(Bb + kr*(GPB*4) + ng*16,
                           Bm + (size_t)(s*32 + kr) * N + n0 + ng*4);
            }
        }
        CP_COMMIT();
    };

    load_stage(0, 0);
    load_stage(1, 1);

    for (int s = 0; s < S; s++) {
        if (s < S - 1) CP_WAIT1(); else CP_WAIT0();
        __syncthreads();
        if (s < S - 2) load_stage(s + 2, (s + 2) % 3);

        const float* Ab = sm + (s % 3) * AW;
        const float* Bb = sm + 3 * AW + (s % 3) * BW;
        #pragma unroll
        for (int ks = 0; ks < 4; ks++) {
            float a[MI][4];
            #pragma unroll
            for (int mi = 0; mi < MI; mi++) {
                int r = wm*(16*MI) + mi*16 + grp;
                int c = ks*8 + tig;
                a[mi][0] = Ab[r * GPA + c];
                a[mi][1] = Ab[(r + 8) * GPA + c];
                a[mi][2] = Ab[r * GPA + c + 4];
                a[mi][3] = Ab[(r + 8) * GPA + c + 4];
            }
            float b[8][2];
            #pragma unroll
            for (int nf = 0; nf < 8; nf++) {
                int n = wn*64 + nf*8 + grp;
                if (BTRANS) {
                    b[nf][0] = Bb[n * GPA + ks*8 + tig];
                    b[nf][1] = Bb[n * GPA + ks*8 + tig + 4];
                } else {
                    b[nf][0] = Bb[(ks*8 + tig) * GPB + n];
                    b[nf][1] = Bb[(ks*8 + tig + 4) * GPB + n];
                }
            }
            #pragma unroll
            for (int mi = 0; mi < MI; mi++)
                #pragma unroll
                for (int nf = 0; nf < 8; nf++)
                    mma_tf32(acc[mi][nf], a[mi], b[nf]);
        }
    }

    #pragma unroll
    for (int mi = 0; mi < MI; mi++)
        #pragma unroll
        for (int hf = 0; hf < 2; hf++) {
            int row = m0 + wm*(16*MI) + mi*16 + grp + hf*8;
            #pragma unroll
            for (int nf = 0; nf < 8; nf++) {
                int col = n0 + wn*64 + nf*8 + tig*2;
                float v0 = acc[mi][nf][hf*2 + 0] + bias[col];
                float v1 = acc[mi][nf][hf*2 + 1] + bias[col + 1];
                if (EPI == 1) { v0 = fmaxf(v0, 0.f); v1 = fmaxf(v1, 0.f); }
                if (EPI == 2) {
                    v0 += add[(size_t)row * N + col];
                    v1 += add[(size_t)row * N + col + 1];
                }
                *(float2*)(C + (size_t)row * N + col) = make_float2(v0, v1);
            }
        }
}

// ---------------- softmax + attn, one CTA per (b, h) --------------------------
__global__ __launch_bounds__(256) void softmax_attn_kernel()
{
    const int b = blockIdx.x, h = blockIdx.y;
    __shared__ float p[64][68];
    __shared__ float vs[64][68];
    const int t = threadIdx.x;
    const int i = t >> 2, q = t & 3;
    const int d0 = q * 16;

    {
        const float* src = g_qkv + (size_t)(i*B_ + b)*(3*E_) + 2*E_ + h*64 + d0;
        #pragma unroll
        for (int e = 0; e < 16; e += 4)
            *(float4*)&vs[i][d0 + e] = *(const float4*)(src + e);
    }
    {
        float w[16];
        const float* wr = g_w + ((size_t)(i*B_ + b)*H_ + h)*T_ + d0;
        #pragma unroll
        for (int e = 0; e < 16; e += 4) {
            float4 v4 = *(const float4*)(wr + e);
            w[e] = v4.x; w[e+1] = v4.y; w[e+2] = v4.z; w[e+3] = v4.w;
        }
        float mx = w[0];
        #pragma unroll
        for (int e = 1; e < 16; e++) mx = fmaxf(mx, w[e]);
        mx = fmaxf(mx, __shfl_xor_sync(~0u, mx, 1));
        mx = fmaxf(mx, __shfl_xor_sync(~0u, mx, 2));
        float s = 0.f;
        #pragma unroll
        for (int e = 0; e < 16; e++) { w[e] = expf(w[e] - mx); s += w[e]; }
        s += __shfl_xor_sync(~0u, s, 1);
        s += __shfl_xor_sync(~0u, s, 2);
        float inv = 1.f / s;
        #pragma unroll
        for (int e = 0; e < 16; e++) p[i][d0 + e] = w[e] * inv;
    }
    __syncthreads();

    float acc[16] = {};
    for (int j = 0; j < 64; j++) {
        float pij = p[i][j];
        #pragma unroll
        for (int e = 0; e < 16; e += 4) {
            float4 v4 = *(float4*)&vs[j][d0 + e];
            acc[e]   = fmaf(pij, v4.x, acc[e]);
            acc[e+1] = fmaf(pij, v4.y, acc[e+1]);
            acc[e+2] = fmaf(pij, v4.z, acc[e+2]);
            acc[e+3] = fmaf(pij, v4.w, acc[e+3]);
        }
    }
    float* dst = g_attn + (size_t)(i*B_ + b)*E_ + h*64 + d0;
    #pragma unroll
    for (int e = 0; e < 16; e += 4)
        *(float4*)(dst + e) = make_float4(acc[e], acc[e+1], acc[e+2], acc[e+3]);
}

// ---------------- layernorm (optional extra fp16 output) ----------------------
__global__ __launch_bounds__(256) void ln_kernel(
    const float* __restrict__ in, const float* __restrict__ g,
    const float* __restrict__ b, float* __restrict__ out,
    __half* __restrict__ hout)
{
    int row = blockIdx.x;
    const float* r = in + (size_t)row * E_;
    int t = threadIdx.x;
    float v0 = r[t], v1 = r[t + 256];
    float s = v0 + v1, sq = v0*v0 + v1*v1;
    #pragma unroll
    for (int o = 16; o; o >>= 1) {
        s  += __shfl_xor_sync(~0u, s,  o);
        sq += __shfl_xor_sync(~0u, sq, o);
    }
    __shared__ float ss[8], ssq[8];
    int w = t >> 5, l = t & 31;
    if (l == 0) { ss[w] = s; ssq[w] = sq; }
    __syncthreads();
    if (w == 0) {
        s  = (l < 8) ? ss[l]  : 0.f;
        sq = (l < 8) ? ssq[l] : 0.f;
        #pragma unroll
        for (int o = 4; o; o >>= 1) {
            s  += __shfl_xor_sync(~0u, s,  o);
            sq += __shfl_xor_sync(~0u, sq, o);
        }
        if (l == 0) { ss[0] = s; ssq[0] = sq; }
    }
    __syncthreads();
    float mu   = ss[0]  * (1.f / E_);
    float var  = ssq[0] * (1.f / E_) - mu * mu;
    float rstd = rsqrtf(var + 1e-5f);
    float o0 = (v0 - mu) * rstd * g[t]       + b[t];
    float o1 = (v1 - mu) * rstd * g[t + 256] + b[t + 256];
    out[(size_t)row*E_ + t]       = o0;
    out[(size_t)row*E_ + t + 256] = o1;
    if (hout) {
        hout[(size_t)row*E_ + t]       = __float2half_rn(o0);
        hout[(size_t)row*E_ + t + 256] = __float2half_rn(o1);
    }
}

// ---------------- launch --------------------------------------------------------
extern "C" void kernel_launch(void* const* d_in, const int* in_sizes, int n_in,
                              void* d_out, int out_size)
{
    const float* x        = (const float*)d_in[0];
    const float* relation = (const float*)d_in[1];
    const float* in_w     = (const float*)d_in[2];
    const float* in_b     = (const float*)d_in[3];
    const float* rel_w    = (const float*)d_in[4];
    const float* rel_b    = (const float*)d_in[5];
    const float* out_w    = (const float*)d_in[6];
    const float* out_b    = (const float*)d_in[7];
    const float* fc1_w    = (const float*)d_in[8];
    const float* fc1_b    = (const float*)d_in[9];
    const float* fc2_w    = (const float*)d_in[10];
    const float* fc2_b    = (const float*)d_in[11];
    const float* ln1_g    = (const float*)d_in[12];
    const float* ln1_b    = (const float*)d_in[13];
    const float* ln2_g    = (const float*)d_in[14];
    const float* ln2_b    = (const float*)d_in[15];
    float* out = (float*)d_out;

    const int SM_BT128 = 3 * (128*GPA + 128*GPA) * 4;   // qkv MI=2
    const int SM_BN64  = 3 * (64*GPA  + 32*GPB) * 4;    // out-proj MI=1

    static float *p_qkv = nullptr, *p_attn, *p_ao, *p_h, *p_f2;
    static __nv_bfloat16* p_arel;
    static __half *p_hh, *p_f1h, *p_w1h, *p_w2h;
    static cudaStream_t s_side;
    static cudaEvent_t ev_fork, ev_join;
    if (!p_qkv) {
        cudaGetSymbolAddress((void**)&p_qkv,  g_qkv);
        cudaGetSymbolAddress((void**)&p_attn, g_attn);
        cudaGetSymbolAddress((void**)&p_ao,   g_ao);
        cudaGetSymbolAddress((void**)&p_h,    g_h);
        cudaGetSymbolAddress((void**)&p_f2,   g_f2);
        cudaGetSymbolAddress((void**)&p_arel, g_arel);
        cudaGetSymbolAddress((void**)&p_hh,   g_hh);
        cudaGetSymbolAddress((void**)&p_f1h,  g_f1h);
        cudaGetSymbolAddress((void**)&p_w1h,  g_w1h);
        cudaGetSymbolAddress((void**)&p_w2h,  g_w2h);
        cudaFuncSetAttribute(relw_mma, cudaFuncAttributeMaxDynamicSharedMemorySize, RELW_SMEM);
        cudaFuncSetAttribute(gemm_h16<1>, cudaFuncAttributeMaxDynamicSharedMemorySize, RELW_SMEM);
        cudaFuncSetAttribute(gemm_h16<2>, cudaFuncAttributeMaxDynamicSharedMemorySize, RELW_SMEM);
        cudaFuncSetAttribute(gemm_tf32<2, true, 0>,  cudaFuncAttributeMaxDynamicSharedMemorySize, SM_BT128);
        cudaFuncSetAttribute(gemm_tf32<1, false, 2>, cudaFuncAttributeMaxDynamicSharedMemorySize, SM_BN64);
        cudaStreamCreateWithFlags(&s_side, cudaStreamNonBlocking);
        cudaEventCreateWithFlags(&ev_fork, cudaEventDisableTiming);
        cudaEventCreateWithFlags(&ev_join, cudaEventDisableTiming);
    }

    dim3 blk(256);

    // ---- fork: cvt_rel on side stream (overlaps main prepasses + qkv) ----------
    cudaEventRecord(ev_fork, 0);
    cudaStreamWaitEvent(s_side, ev_fork, 0);
    cvt_rel<<<ROWS_ * E_ / (8 * 256), 256, 0, s_side>>>(relation, p_arel);
    cudaEventRecord(ev_join, s_side);

    // main: weight prepasses (fp16 FFN weights + bf16 relation weights) + qkv
    cvt_f16<<<E_ * F_ / (8 * 256), 256>>>(fc1_w, p_w1h);
    cvt_f16<<<F_ * E_ / (8 * 256), 256>>>(fc2_w, p_w2h);
    build_bw<<<1024, 256>>>(rel_w);
    gemm_tf32<2, true, 0><<<dim3(1536/128, TB_/128), blk, SM_BT128>>>(x, in_w, in_b, nullptr, p_qkv, TB_, 3*E_, E_);

    cudaStreamWaitEvent(0, ev_join, 0);

    // 2. relation GEMM (bf16 HMMA) + fused logits
    relw_mma<<<dim3(H_, ROWS_/128), blk, RELW_SMEM>>>(rel_b);

    // 3. softmax + attn, CTA per (b,h)
    softmax_attn_kernel<<<dim3(B_, H_), 256>>>();

    // 4. out proj + residual  (tf32 MI=1)
    gemm_tf32<1, false, 2><<<dim3(E_/128, TB_/64), blk, SM_BN64>>>(p_attn, out_w, out_b, x, p_ao, TB_, E_, E_);

    // 5. LN1 -> h (fp32) + h (fp16)
    ln_kernel<<<TB_, 256>>>(p_ao, ln1_g, ln1_b, p_h, p_hh);

    // 6. fc1 + relu  (fp16 HMMA, writes fp16 directly)
    gemm_h16<1><<<dim3(F_/128, TB_/128), blk, RELW_SMEM>>>(p_hh, p_w1h, fc1_b, nullptr, p_f1h, TB_, F_, E_);

    // 7. fc2 + residual h  (fp16 HMMA)
    gemm_h16<2><<<dim3(E_/128, TB_/128), blk, RELW_SMEM>>>(p_f1h, p_w2h, fc2_b, p_h, p_f2, TB_, E_, F_);

    // 8. LN2 -> out
    ln_kernel<<<TB_, 256>>>(p_f2, ln2_g, ln2_b, out, nullptr);
}

// round 16
// speedup vs baseline: 1.0955x; 1.0121x over previous
#include <cuda_runtime.h>
#include <cuda_bf16.h>
#include <cuda_fp16.h>
#include <cstdint>

#define T_  64
#define B_  32
#define E_  512
#define H_  8
#define F_  2048
#define TB_ (T_*B_)        // 2048
#define ROWS_ (T_*T_*B_)   // 131072

// ---------------- scratch ----------------------------------------------------
__device__ float g_qkv[TB_ * 3 * E_];
__device__ float g_w[TB_ * H_ * T_];
__device__ float g_ao[TB_ * E_];
__device__ float g_h[TB_ * E_];
__device__ float g_f2[TB_ * E_];
__device__ __nv_bfloat16 g_arel[(size_t)ROWS_ * E_];   // relation in bf16 (134MB)
__device__ __nv_bfloat16 g_bw[H_ * E_ * 128];          // [h][k][2d interleaved ra/rb]
__device__ __half g_xh[TB_ * E_];                      // x fp16 (qkv A)
__device__ __half g_wqkT[E_ * 3 * E_];                 // in_w^T fp16 [K=512][N=1536]
__device__ __half g_woh[E_ * E_];                      // out_w fp16 [K,N]
__device__ __half g_attnh[TB_ * E_];                   // attn fp16 (out-proj A)
__device__ __half g_hh[TB_ * E_];                      // h fp16 (fc1 A)
__device__ __half g_f1h[TB_ * F_];                     // relu(fc1) fp16 (fc2 A)
__device__ __half g_w1h[E_ * F_];                      // fc1_w fp16
__device__ __half g_w2h[F_ * E_];                      // fc2_w fp16

// ---------------- helpers ------------------------------------------------------
__device__ __forceinline__ uint32_t smem_u32(const void* p) {
    return (uint32_t)__cvta_generic_to_shared(p);
}
__device__ __forceinline__ void ldsm_x4(uint32_t& r0, uint32_t& r1, uint32_t& r2, uint32_t& r3, uint32_t a) {
    asm volatile("ldmatrix.sync.aligned.m8n8.x4.shared.b16 {%0,%1,%2,%3},[%4];"
                 : "=r"(r0), "=r"(r1), "=r"(r2), "=r"(r3) : "r"(a));
}
__device__ __forceinline__ void ldsm_x4_t(uint32_t& r0, uint32_t& r1, uint32_t& r2, uint32_t& r3, uint32_t a) {
    asm volatile("ldmatrix.sync.aligned.m8n8.x4.trans.shared.b16 {%0,%1,%2,%3},[%4];"
                 : "=r"(r0), "=r"(r1), "=r"(r2), "=r"(r3) : "r"(a));
}
__device__ __forceinline__ void mma16816(float* c, const uint32_t* a, const uint32_t* b) {
    asm volatile("mma.sync.aligned.m16n8k16.row.col.f32.bf16.bf16.f32 "
                 "{%0,%1,%2,%3},{%4,%5,%6,%7},{%8,%9},{%0,%1,%2,%3};"
                 : "+f"(c[0]), "+f"(c[1]), "+f"(c[2]), "+f"(c[3])
                 : "r"(a[0]), "r"(a[1]), "r"(a[2]), "r"(a[3]), "r"(b[0]), "r"(b[1]));
}
__device__ __forceinline__ void mma16816h(float* c, const uint32_t* a, const uint32_t* b) {
    asm volatile("mma.sync.aligned.m16n8k16.row.col.f32.f16.f16.f32 "
                 "{%0,%1,%2,%3},{%4,%5,%6,%7},{%8,%9},{%0,%1,%2,%3};"
                 : "+f"(c[0]), "+f"(c[1]), "+f"(c[2]), "+f"(c[3])
                 : "r"(a[0]), "r"(a[1]), "r"(a[2]), "r"(a[3]), "r"(b[0]), "r"(b[1]));
}
__device__ __forceinline__ uint32_t f2bf2(float x, float y) {
    __nv_bfloat162 t = __floats2bfloat162_rn(x, y);
    return *reinterpret_cast<uint32_t*>(&t);
}
__device__ __forceinline__ uint32_t f2h2(float x, float y) {
    __half2 t = __floats2half2_rn(x, y);
    return *reinterpret_cast<uint32_t*>(&t);
}
#define CP_ASYNC16(saddr, gptr) \
    asm volatile("cp.async.cg.shared.global [%0], [%1], 16;" :: "r"(saddr), "l"(gptr) : "memory")
#define CP_COMMIT() asm volatile("cp.async.commit_group;" ::: "memory")
#define CP_WAIT1()  asm volatile("cp.async.wait_group 1;" ::: "memory")
#define CP_WAIT0()  asm volatile("cp.async.wait_group 0;" ::: "memory")

// ---------------- prepass: relation fp32 -> bf16 (streaming hints) ------------
__global__ __launch_bounds__(256) void cvt_rel(const float* __restrict__ rel,
                                               __nv_bfloat16* __restrict__ dst)
{
    size_t i = ((size_t)blockIdx.x * 256 + threadIdx.x) * 8;
    float4 a = __ldcs((const float4*)(rel + i));
    float4 b = __ldcs((const float4*)(rel + i + 4));
    uint4 v = make_uint4(f2bf2(a.x, a.y), f2bf2(a.z, a.w),
                         f2bf2(b.x, b.y), f2bf2(b.z, b.w));
    __stcs((uint4*)((char*)dst + i * 2), v);
}

// ---------------- prepass: fp32 -> fp16 ---------------------------------------
__global__ __launch_bounds__(256) void cvt_f16(const float* __restrict__ src,
                                               __half* __restrict__ dst)
{
    size_t i = ((size_t)blockIdx.x * 256 + threadIdx.x) * 8;
    float4 a = *(const float4*)(src + i);
    float4 b = *(const float4*)(src + i + 4);
    uint4 v = make_uint4(f2h2(a.x, a.y), f2h2(a.z, a.w),
                         f2h2(b.x, b.y), f2h2(b.z, b.w));
    *(uint4*)((char*)dst + i * 2) = v;
}

// ---------------- prepass: transpose+cvt in_w [N,K] -> [K,N] fp16 -------------
__global__ __launch_bounds__(256) void cvt_wT(const float* __restrict__ src,
                                              __half* __restrict__ dst, int N, int K)
{
    int idx = blockIdx.x * 256 + threadIdx.x;   // N*K
    int n = idx / K, k = idx - n * K;
    dst[(size_t)k * N + n] = __float2half_rn(src[idx]);
}

// ---------------- prepass: interleaved bf16 weight tiles [h][k][128] ----------
__global__ __launch_bounds__(256) void build_bw(const float* __restrict__ relw)
{
    int idx = blockIdx.x * 256 + threadIdx.x;    // 262144
    int d = idx & 63;
    int k = (idx >> 6) & 511;
    int h = idx >> 15;
    g_bw[((size_t)h*E_ + k) * 128 + 2*d    ] = __float2bfloat16(relw[(size_t)k*(2*E_) + h*64 + d]);
    g_bw[((size_t)h*E_ + k) * 128 + 2*d + 1] = __float2bfloat16(relw[(size_t)k*(2*E_) + E_ + h*64 + d]);
}

// ---------------- fused relation GEMM (bf16 HMMA, 3-stage, 2 CTAs/SM) ---------
#define RSA_STRIDE 16384
#define RSB_BASE   49152
#define RSB_STRIDE 16384
#define RELW_SMEM  98304
__global__ void __launch_bounds__(256, 2) relw_mma(const float* __restrict__ relb)
{
    extern __shared__ char smem[];
    const uint32_t AsBase = smem_u32(smem);
    const uint32_t BsBase = AsBase + RSB_BASE;
    float* red = (float*)smem;

    const int h   = blockIdx.x;
    const int n0  = blockIdx.y * 128;
    const int tid = threadIdx.x;
    const int lane = tid & 31, warp = tid >> 5;
    const int warp_m = warp >> 1, warp_n = warp & 1;

    float acc[2][8][4];
    #pragma unroll
    for (int i = 0; i < 2; i++)
        #pragma unroll
        for (int j = 0; j < 8; j++)
            #pragma unroll
            for (int k = 0; k < 4; k++) acc[i][j][k] = 0.f;

    const __nv_bfloat16* Ag = g_arel + (size_t)n0 * E_;
    const __nv_bfloat16* Bg = g_bw + (size_t)h * E_ * 128;

    auto load_stage = [&](int s, int buf) {
        uint32_t Ab = AsBase + buf * RSA_STRIDE;
        #pragma unroll
        for (int c = 0; c < 4; c++) {
            int idx = c * 256 + tid;
            int row = idx >> 3, cg = idx & 7;
            CP_ASYNC16(Ab + row*128 + (((cg ^ (row & 7)) << 4)),
                       Ag + (size_t)row * E_ + s*64 + cg*8);
        }
        uint32_t Bb = BsBase + buf * RSB_STRIDE;
        #pragma unroll
        for (int c = 0; c < 4; c++) {
            int idx = c * 256 + tid;
            int kr = idx >> 4, ng = idx & 15;
            CP_ASYNC16(Bb + kr*256 + (((ng ^ (kr & 7)) << 4)),
                       Bg + (size_t)(s*64 + kr) * 128 + ng*8);
        }
        CP_COMMIT();
    };

    load_stage(0, 0);
    load_stage(1, 1);

    const int a_r  = warp_m*32 + (lane & 15);
    const int a_kc = (lane >> 4) << 3;
    const int b_kr = lane & 15;
    const int b_nc = warp_n*64 + ((lane >> 4) << 3);

    #pragma unroll
    for (int s = 0; s < 8; s++) {
        if (s < 7) CP_WAIT1(); else CP_WAIT0();
        __syncthreads();
        if (s < 6) load_stage(s + 2, (s + 2) % 3);

        const uint32_t Ab = AsBase + (s % 3) * RSA_STRIDE;
        const uint32_t Bb = BsBase + (s % 3) * RSB_STRIDE;

        #pragma unroll
        for (int ks = 0; ks < 4; ks++) {
            uint32_t a[2][4];
            #pragma unroll
            for (int mi = 0; mi < 2; mi++) {
                int r  = a_r + mi*16;
                int kc = a_kc + ks*16;
                ldsm_x4(a[mi][0], a[mi][1], a[mi][2], a[mi][3],
                        Ab + r*128 + ((((kc >> 3) ^ (r & 7)) << 4)));
            }
            uint32_t b[8][2];
            #pragma unroll
            for (int g = 0; g < 4; g++) {
                int krow = b_kr + ks*16;
                int ncol = b_nc + g*16;
                ldsm_x4_t(b[2*g][0], b[2*g][1], b[2*g+1][0], b[2*g+1][1],
                          Bb + krow*256 + ((((ncol >> 3) ^ (krow & 7)) << 4)));
            }
            #pragma unroll
            for (int mi = 0; mi < 2; mi++)
                #pragma unroll
                for (int nf = 0; nf < 8; nf++)
                    mma16816(acc[mi][nf], a[mi], b[nf]);
        }
    }

    // ---- fused epilogue --------------------------------------------------------
    const int tig = lane & 3, grp = lane >> 2;
    float part[2][2] = {{0.f, 0.f}, {0.f, 0.f}};
    #pragma unroll
    for (int nf = 0; nf < 8; nf++) {
        int d = warp_n*32 + nf*4 + tig;
        float bra = relb[h*64 + d];
        float brb = relb[E_ + h*64 + d];
        #pragma unroll
        for (int mi = 0; mi < 2; mi++)
            #pragma unroll
            for (int hf = 0; hf < 2; hf++) {
                int r  = warp_m*32 + mi*16 + grp + hf*8;
                int n  = n0 + r;
                int b  = n & 31;
                int ji = n >> 5;
                int ii = ji & 63, jj = ji >> 6;
                float q = g_qkv[(size_t)(ii*B_ + b) * (3*E_) + h*64 + d];
                float k = g_qkv[(size_t)(jj*B_ + b) * (3*E_) + E_ + h*64 + d];
                part[mi][hf] += (acc[mi][nf][hf*2+0] + bra + q) * (acc[mi][nf][hf*2+1] + brb + k);
            }
    }
    #pragma unroll
    for (int mi = 0; mi < 2; mi++)
        #pragma unroll
        for (int hf = 0; hf < 2; hf++) {
            float v = part[mi][hf];
            v += __shfl_xor_sync(~0u, v, 1);
            v += __shfl_xor_sync(~0u, v, 2);
            part[mi][hf] = v;
        }
    __syncthreads();
    if (tig == 0) {
        #pragma unroll
        for (int mi = 0; mi < 2; mi++)
            #pragma unroll
            for (int hf = 0; hf < 2; hf++) {
                int r = warp_m*32 + mi*16 + grp + hf*8;
                red[r*2 + warp_n] = part[mi][hf];
            }
    }
    __syncthreads();
    if (tid < 128) {
        int n  = n0 + tid;
        int b  = n & 31;
        int ji = n >> 5;
        int ii = ji & 63, jj = ji >> 6;
        g_w[((size_t)(ii*B_ + b) * H_ + h) * T_ + jj] =
            (red[tid*2] + red[tid*2 + 1]) * 0.015625f;
    }
}

// ---------------- fp16 GEMM: 128x128 tile, K-stage 64, 3-stage, 2 CTAs/SM -----
// A [M,K] half row-major, B [K,N] half row-major.
// EPI 0: +bias, write float. EPI 1: relu, write half. EPI 2: +add fp32, write float.
template<int EPI>
__global__ void __launch_bounds__(256, 2) gemm_h16(
    const __half* __restrict__ A, const __half* __restrict__ Bm,
    const float* __restrict__ bias, const float* __restrict__ add,
    void* __restrict__ Cv, int M, int N, int K)
{
    extern __shared__ char smem[];
    const uint32_t AsBase = smem_u32(smem);
    const uint32_t BsBase = AsBase + RSB_BASE;

    const int tid = threadIdx.x;
    const int lane = tid & 31, warp = tid >> 5;
    const int warp_m = warp >> 1, warp_n = warp & 1;
    const int m0 = blockIdx.y * 128;
    const int n0 = blockIdx.x * 128;

    float acc[2][8][4];
    #pragma unroll
    for (int i = 0; i < 2; i++)
        #pragma unroll
        for (int j = 0; j < 8; j++)
            #pragma unroll
            for (int k = 0; k < 4; k++) acc[i][j][k] = 0.f;

    const __half* Ag = A + (size_t)m0 * K;
    const int S = K >> 6;

    auto load_stage = [&](int s, int buf) {
        uint32_t Ab = AsBase + buf * RSA_STRIDE;
        #pragma unroll
        for (int c = 0; c < 4; c++) {
            int idx = c * 256 + tid;
            int row = idx >> 3, cg = idx & 7;
            CP_ASYNC16(Ab + row*128 + (((cg ^ (row & 7)) << 4)),
                       Ag + (size_t)row * K + s*64 + cg*8);
        }
        uint32_t Bb = BsBase + buf * RSB_STRIDE;
        #pragma unroll
        for (int c = 0; c < 4; c++) {
            int idx = c * 256 + tid;
            int kr = idx >> 4, ng = idx & 15;
            CP_ASYNC16(Bb + kr*256 + (((ng ^ (kr & 7)) << 4)),
                       Bm + (size_t)(s*64 + kr) * N + n0 + ng*8);
        }
        CP_COMMIT();
    };

    load_stage(0, 0);
    load_stage(1, 1);

    const int a_r  = warp_m*32 + (lane & 15);
    const int a_kc = (lane >> 4) << 3;
    const int b_kr = lane & 15;
    const int b_nc = warp_n*64 + ((lane >> 4) << 3);

    for (int s = 0; s < S; s++) {
        if (s < S - 1) CP_WAIT1(); else CP_WAIT0();
        __syncthreads();
        if (s < S - 2) load_stage(s + 2, (s + 2) % 3);

        const uint32_t Ab = AsBase + (s % 3) * RSA_STRIDE;
        const uint32_t Bb = BsBase + (s % 3) * RSB_STRIDE;

        #pragma unroll
        for (int ks = 0; ks < 4; ks++) {
            uint32_t a[2][4];
            #pragma unroll
            for (int mi = 0; mi < 2; mi++) {
                int r  = a_r + mi*16;
                int kc = a_kc + ks*16;
                ldsm_x4(a[mi][0], a[mi][1], a[mi][2], a[mi][3],
                        Ab + r*128 + ((((kc >> 3) ^ (r & 7)) << 4)));
            }
            uint32_t b[8][2];
            #pragma unroll
            for (int g = 0; g < 4; g++) {
                int krow = b_kr + ks*16;
                int ncol = b_nc + g*16;
                ldsm_x4_t(b[2*g][0], b[2*g][1], b[2*g+1][0], b[2*g+1][1],
                          Bb + krow*256 + ((((ncol >> 3) ^ (krow & 7)) << 4)));
            }
            #pragma unroll
            for (int mi = 0; mi < 2; mi++)
                #pragma unroll
                for (int nf = 0; nf < 8; nf++)
                    mma16816h(acc[mi][nf], a[mi], b[nf]);
        }
    }

    // ---- epilogue ---------------------------------------------------------------
    const int tig = lane & 3, grp = lane >> 2;
    #pragma unroll
    for (int mi = 0; mi < 2; mi++)
        #pragma unroll
        for (int hf = 0; hf < 2; hf++) {
            int row = m0 + warp_m*32 + mi*16 + grp + hf*8;
            #pragma unroll
            for (int nf = 0; nf < 8; nf++) {
                int col = n0 + warp_n*64 + nf*8 + tig*2;
                float v0 = acc[mi][nf][hf*2 + 0] + bias[col];
                float v1 = acc[mi][nf][hf*2 + 1] + bias[col + 1];
                if (EPI == 1) {
                    v0 = fmaxf(v0, 0.f); v1 = fmaxf(v1, 0.f);
                    *(uint32_t*)((__half*)Cv + (size_t)row * N + col) = f2h2(v0, v1);
                } else {
                    if (EPI == 2) {
                        v0 += add[(size_t)row * N + col];
                        v1 += add[(size_t)row * N + col + 1];
                    }
                    *(float2*)((float*)Cv + (size_t)row * N + col) = make_float2(v0, v1);
                }
            }
        }
}

// ---------------- softmax + attn, one CTA per (b, h), fp16 output -------------
__global__ __launch_bounds__(256) void softmax_attn_kernel()
{
    const int b = blockIdx.x, h = blockIdx.y;
    __shared__ float p[64][68];
    __shared__ float vs[64][68];
    const int t = threadIdx.x;
    const int i = t >> 2, q = t & 3;
    const int d0 = q * 16;

    {
        const float* src = g_qkv + (size_t)(i*B_ + b)*(3*E_) + 2*E_ + h*64 + d0;
        #pragma unroll
        for (int e = 0; e < 16; e += 4)
            *(float4*)&vs[i][d0 + e] = *(const float4*)(src + e);
    }
    {
        float w[16];
        const float* wr = g_w + ((size_t)(i*B_ + b)*H_ + h)*T_ + d0;
        #pragma unroll
        for (int e = 0; e < 16; e += 4) {
            float4 v4 = *(const float4*)(wr + e);
            w[e] = v4.x; w[e+1] = v4.y; w[e+2] = v4.z; w[e+3] = v4.w;
        }
        float mx = w[0];
        #pragma unroll
        for (int e = 1; e < 16; e++) mx = fmaxf(mx, w[e]);
        mx = fmaxf(mx, __shfl_xor_sync(~0u, mx, 1));
        mx = fmaxf(mx, __shfl_xor_sync(~0u, mx, 2));
        float s = 0.f;
        #pragma unroll
        for (int e = 0; e < 16; e++) { w[e] = expf(w[e] - mx); s += w[e]; }
        s += __shfl_xor_sync(~0u, s, 1);
        s += __shfl_xor_sync(~0u, s, 2);
        float inv = 1.f / s;
        #pragma unroll
        for (int e = 0; e < 16; e++) p[i][d0 + e] = w[e] * inv;
    }
    __syncthreads();

    float acc[16] = {};
    for (int j = 0; j < 64; j++) {
        float pij = p[i][j];
        #pragma unroll
        for (int e = 0; e < 16; e += 4) {
            float4 v4 = *(float4*)&vs[j][d0 + e];
            acc[e]   = fmaf(pij, v4.x, acc[e]);
            acc[e+1] = fmaf(pij, v4.y, acc[e+1]);
            acc[e+2] = fmaf(pij, v4.z, acc[e+2]);
            acc[e+3] = fmaf(pij, v4.w, acc[e+3]);
        }
    }
    __half* dst = g_attnh + (size_t)(i*B_ + b)*E_ + h*64 + d0;
    #pragma unroll
    for (int e = 0; e < 16; e += 4)
        *(uint2*)(dst + e) = make_uint2(f2h2(acc[e], acc[e+1]), f2h2(acc[e+2], acc[e+3]));
}

// ---------------- layernorm (optional extra fp16 output) ----------------------
__global__ __launch_bounds__(256) void ln_kernel(
    const float* __restrict__ in, const float* __restrict__ g,
    const float* __restrict__ b, float* __restrict__ out,
    __half* __restrict__ hout)
{
    int row = blockIdx.x;
    const float* r = in + (size_t)row * E_;
    int t = threadIdx.x;
    float v0 = r[t], v1 = r[t + 256];
    float s = v0 + v1, sq = v0*v0 + v1*v1;
    #pragma unroll
    for (int o = 16; o; o >>= 1) {
        s  += __shfl_xor_sync(~0u, s,  o);
        sq += __shfl_xor_sync(~0u, sq, o);
    }
    __shared__ float ss[8], ssq[8];
    int w = t >> 5, l = t & 31;
    if (l == 0) { ss[w] = s; ssq[w] = sq; }
    __syncthreads();
    if (w == 0) {
        s  = (l < 8) ? ss[l]  : 0.f;
        sq = (l < 8) ? ssq[l] : 0.f;
        #pragma unroll
        for (int o = 4; o; o >>= 1) {
            s  += __shfl_xor_sync(~0u, s,  o);
            sq += __shfl_xor_sync(~0u, sq, o);
        }
        if (l == 0) { ss[0] = s; ssq[0] = sq; }
    }
    __syncthreads();
    float mu   = ss[0]  * (1.f / E_);
    float var  = ssq[0] * (1.f / E_) - mu * mu;
    float rstd = rsqrtf(var + 1e-5f);
    float o0 = (v0 - mu) * rstd * g[t]       + b[t];
    float o1 = (v1 - mu) * rstd * g[t + 256] + b[t + 256];
    out[(size_t)row*E_ + t]       = o0;
    out[(size_t)row*E_ + t + 256] = o1;
    if (hout) {
        hout[(size_t)row*E_ + t]       = __float2half_rn(o0);
        hout[(size_t)row*E_ + t + 256] = __float2half_rn(o1);
    }
}

// ---------------- launch --------------------------------------------------------
extern "C" void kernel_launch(void* const* d_in, const int* in_sizes, int n_in,
                              void* d_out, int out_size)
{
    const float* x        = (const float*)d_in[0];
    const float* relation = (const float*)d_in[1];
    const float* in_w     = (const float*)d_in[2];
    const float* in_b     = (const float*)d_in[3];
    const float* rel_w    = (const float*)d_in[4];
    const float* rel_b    = (const float*)d_in[5];
    const float* out_w    = (const float*)d_in[6];
    const float* out_b    = (const float*)d_in[7];
    const float* fc1_w    = (const float*)d_in[8];
    const float* fc1_b    = (const float*)d_in[9];
    const float* fc2_w    = (const float*)d_in[10];
    const float* fc2_b    = (const float*)d_in[11];
    const float* ln1_g    = (const float*)d_in[12];
    const float* ln1_b    = (const float*)d_in[13];
    const float* ln2_g    = (const float*)d_in[14];
    const float* ln2_b    = (const float*)d_in[15];
    float* out = (float*)d_out;

    static float *p_qkv = nullptr, *p_ao, *p_h, *p_f2;
    static __nv_bfloat16* p_arel;
    static __half *p_xh, *p_wqkT, *p_woh, *p_attnh, *p_hh, *p_f1h, *p_w1h, *p_w2h;
    static cudaStream_t s_side;
    static cudaEvent_t ev_fork, ev_join;
    if (!p_qkv) {
        cudaGetSymbolAddress((void**)&p_qkv,  g_qkv);
        cudaGetSymbolAddress((void**)&p_ao,   g_ao);
        cudaGetSymbolAddress((void**)&p_h,    g_h);
        cudaGetSymbolAddress((void**)&p_f2,   g_f2);
        cudaGetSymbolAddress((void**)&p_arel, g_arel);
        cudaGetSymbolAddress((void**)&p_xh,   g_xh);
        cudaGetSymbolAddress((void**)&p_wqkT, g_wqkT);
        cudaGetSymbolAddress((void**)&p_woh,  g_woh);
        cudaGetSymbolAddress((void**)&p_attnh,g_attnh);
        cudaGetSymbolAddress((void**)&p_hh,   g_hh);
        cudaGetSymbolAddress((void**)&p_f1h,  g_f1h);
        cudaGetSymbolAddress((void**)&p_w1h,  g_w1h);
        cudaGetSymbolAddress((void**)&p_w2h,  g_w2h);
        cudaFuncSetAttribute(relw_mma, cudaFuncAttributeMaxDynamicSharedMemorySize, RELW_SMEM);
        cudaFuncSetAttribute(gemm_h16<0>, cudaFuncAttributeMaxDynamicSharedMemorySize, RELW_SMEM);
        cudaFuncSetAttribute(gemm_h16<1>, cudaFuncAttributeMaxDynamicSharedMemorySize, RELW_SMEM);
        cudaFuncSetAttribute(gemm_h16<2>, cudaFuncAttributeMaxDynamicSharedMemorySize, RELW_SMEM);
        cudaStreamCreateWithFlags(&s_side, cudaStreamNonBlocking);
        cudaEventCreateWithFlags(&ev_fork, cudaEventDisableTiming);
        cudaEventCreateWithFlags(&ev_join, cudaEventDisableTiming);
    }

    dim3 blk(256);

    // ---- fork: cvt_rel on side stream (overlaps main prepasses + qkv) ----------
    cudaEventRecord(ev_fork, 0);
    cudaStreamWaitEvent(s_side, ev_fork, 0);
    cvt_rel<<<ROWS_ * E_ / (8 * 256), 256, 0, s_side>>>(relation, p_arel);
    cudaEventRecord(ev_join, s_side);

    // main: fp16 prepasses + qkv
    cvt_f16<<<TB_ * E_ / (8 * 256), 256>>>(x, p_xh);
    cvt_wT<<<(3*E_) * E_ / 256, 256>>>(in_w, p_wqkT, 3*E_, E_);
    cvt_f16<<<E_ * E_ / (8 * 256), 256>>>(out_w, p_woh);
    cvt_f16<<<E_ * F_ / (8 * 256), 256>>>(fc1_w, p_w1h);
    cvt_f16<<<F_ * E_ / (8 * 256), 256>>>(fc2_w, p_w2h);
    build_bw<<<1024, 256>>>(rel_w);

    // 1. qkv (fp16 HMMA): [2048 x 1536], K=512
    gemm_h16<0><<<dim3(1536/128, TB_/128), blk, RELW_SMEM>>>(p_xh, p_wqkT, in_b, nullptr, p_qkv, TB_, 3*E_, E_);

    cudaStreamWaitEvent(0, ev_join, 0);

    // 2. relation GEMM (bf16 HMMA) + fused logits
    relw_mma<<<dim3(H_, ROWS_/128), blk, RELW_SMEM>>>(rel_b);

    // 3. softmax + attn (fp16 out), CTA per (b,h)
    softmax_attn_kernel<<<dim3(B_, H_), 256>>>();

    // 4. out proj + residual x  (fp16 HMMA)
    gemm_h16<2><<<dim3(E_/128, TB_/128), blk, RELW_SMEM>>>(p_attnh, p_woh, out_b, x, p_ao, TB_, E_, E_);

    // 5. LN1 -> h (fp32) + h (fp16)
    ln_kernel<<<TB_, 256>>>(p_ao, ln1_g, ln1_b, p_h, p_hh);

    // 6. fc1 + relu  (fp16 HMMA, fp16 out)
    gemm_h16<1><<<dim3(F_/128, TB_/128), blk, RELW_SMEM>>>(p_hh, p_w1h, fc1_b, nullptr, p_f1h, TB_, F_, E_);

    // 7. fc2 + residual h  (fp16 HMMA)
    gemm_h16<2><<<dim3(E_/128, TB_/128), blk, RELW_SMEM>>>(p_f1h, p_w2h, fc2_b, p_h, p_f2, TB_, E_, F_);

    // 8. LN2 -> out
    ln_kernel<<<TB_, 256>>>(p_f2, ln2_g, ln2_b, out, nullptr);
}

// round 17
// speedup vs baseline: 1.1188x; 1.0213x over previous
#include <cuda_runtime.h>
#include <cuda_bf16.h>
#include <cuda_fp16.h>
#include <cstdint>

#define T_  64
#define B_  32
#define E_  512
#define H_  8
#define F_  2048
#define TB_ (T_*B_)        // 2048
#define ROWS_ (T_*T_*B_)   // 131072

// ---------------- scratch ----------------------------------------------------
__device__ float g_qkv[TB_ * 3 * E_];
__device__ float g_w[TB_ * H_ * T_];
__device__ float g_ao[TB_ * E_];
__device__ float g_h[TB_ * E_];
__device__ float g_f2[TB_ * E_];
__device__ __nv_bfloat16 g_arel[(size_t)ROWS_ * E_];   // relation in bf16 (134MB)
__device__ __nv_bfloat16 g_bw[H_ * E_ * 128];          // [h][k][2d interleaved ra/rb]
__device__ __half g_xh[TB_ * E_];                      // x fp16 (qkv A)
__device__ __half g_wqkT[E_ * 3 * E_];                 // in_w^T fp16 [K=512][N=1536]
__device__ __half g_woh[E_ * E_];                      // out_w fp16 [K,N]
__device__ __half g_attnh[TB_ * E_];                   // attn fp16 (out-proj A)
__device__ __half g_hh[TB_ * E_];                      // h fp16 (fc1 A)
__device__ __half g_f1h[TB_ * F_];                     // relu(fc1) fp16 (fc2 A)
__device__ __half g_w1h[E_ * F_];                      // fc1_w fp16
__device__ __half g_w2h[F_ * E_];                      // fc2_w fp16

// ---------------- helpers ------------------------------------------------------
__device__ __forceinline__ uint32_t smem_u32(const void* p) {
    return (uint32_t)__cvta_generic_to_shared(p);
}
__device__ __forceinline__ void ldsm_x4(uint32_t& r0, uint32_t& r1, uint32_t& r2, uint32_t& r3, uint32_t a) {
    asm volatile("ldmatrix.sync.aligned.m8n8.x4.shared.b16 {%0,%1,%2,%3},[%4];"
                 : "=r"(r0), "=r"(r1), "=r"(r2), "=r"(r3) : "r"(a));
}
__device__ __forceinline__ void ldsm_x4_t(uint32_t& r0, uint32_t& r1, uint32_t& r2, uint32_t& r3, uint32_t a) {
    asm volatile("ldmatrix.sync.aligned.m8n8.x4.trans.shared.b16 {%0,%1,%2,%3},[%4];"
                 : "=r"(r0), "=r"(r1), "=r"(r2), "=r"(r3) : "r"(a));
}
__device__ __forceinline__ void mma16816(float* c, const uint32_t* a, const uint32_t* b) {
    asm volatile("mma.sync.aligned.m16n8k16.row.col.f32.bf16.bf16.f32 "
                 "{%0,%1,%2,%3},{%4,%5,%6,%7},{%8,%9},{%0,%1,%2,%3};"
                 : "+f"(c[0]), "+f"(c[1]), "+f"(c[2]), "+f"(c[3])
                 : "r"(a[0]), "r"(a[1]), "r"(a[2]), "r"(a[3]), "r"(b[0]), "r"(b[1]));
}
__device__ __forceinline__ void mma16816h(float* c, const uint32_t* a, const uint32_t* b) {
    asm volatile("mma.sync.aligned.m16n8k16.row.col.f32.f16.f16.f32 "
                 "{%0,%1,%2,%3},{%4,%5,%6,%7},{%8,%9},{%0,%1,%2,%3};"
                 : "+f"(c[0]), "+f"(c[1]), "+f"(c[2]), "+f"(c[3])
                 : "r"(a[0]), "r"(a[1]), "r"(a[2]), "r"(a[3]), "r"(b[0]), "r"(b[1]));
}
__device__ __forceinline__ uint32_t f2bf2(float x, float y) {
    __nv_bfloat162 t = __floats2bfloat162_rn(x, y);
    return *reinterpret_cast<uint32_t*>(&t);
}
__device__ __forceinline__ uint32_t f2h2(float x, float y) {
    __half2 t = __floats2half2_rn(x, y);
    return *reinterpret_cast<uint32_t*>(&t);
}
#define CP_ASYNC16(saddr, gptr) \
    asm volatile("cp.async.cg.shared.global [%0], [%1], 16;" :: "r"(saddr), "l"(gptr) : "memory")
#define CP_COMMIT() asm volatile("cp.async.commit_group;" ::: "memory")
#define CP_WAIT1()  asm volatile("cp.async.wait_group 1;" ::: "memory")
#define CP_WAIT0()  asm volatile("cp.async.wait_group 0;" ::: "memory")

// ---------------- prepass: relation fp32 -> bf16 (MLP-4, streaming) -----------
__global__ __launch_bounds__(256) void cvt_rel(const float* __restrict__ rel,
                                               __nv_bfloat16* __restrict__ dst)
{
    size_t i = ((size_t)blockIdx.x * 256 + threadIdx.x) * 16;
    float4 a = __ldcs((const float4*)(rel + i));
    float4 b = __ldcs((const float4*)(rel + i + 4));
    float4 c = __ldcs((const float4*)(rel + i + 8));
    float4 d = __ldcs((const float4*)(rel + i + 12));
    uint4 v0 = make_uint4(f2bf2(a.x, a.y), f2bf2(a.z, a.w),
                          f2bf2(b.x, b.y), f2bf2(b.z, b.w));
    uint4 v1 = make_uint4(f2bf2(c.x, c.y), f2bf2(c.z, c.w),
                          f2bf2(d.x, d.y), f2bf2(d.z, d.w));
    __stcs((uint4*)((char*)dst + i * 2), v0);
    __stcs((uint4*)((char*)dst + i * 2 + 16), v1);
}

// ---------------- prepass: fp32 -> fp16 ---------------------------------------
__global__ __launch_bounds__(256) void cvt_f16(const float* __restrict__ src,
                                               __half* __restrict__ dst)
{
    size_t i = ((size_t)blockIdx.x * 256 + threadIdx.x) * 8;
    float4 a = *(const float4*)(src + i);
    float4 b = *(const float4*)(src + i + 4);
    uint4 v = make_uint4(f2h2(a.x, a.y), f2h2(a.z, a.w),
                         f2h2(b.x, b.y), f2h2(b.z, b.w));
    *(uint4*)((char*)dst + i * 2) = v;
}

// ---------------- prepass: transpose+cvt in_w [N,K] -> [K,N] fp16 -------------
__global__ __launch_bounds__(256) void cvt_wT(const float* __restrict__ src,
                                              __half* __restrict__ dst, int N, int K)
{
    int idx = blockIdx.x * 256 + threadIdx.x;   // N*K
    int n = idx / K, k = idx - n * K;
    dst[(size_t)k * N + n] = __float2half_rn(src[idx]);
}

// ---------------- prepass: interleaved bf16 weight tiles [h][k][128] ----------
__global__ __launch_bounds__(256) void build_bw(const float* __restrict__ relw)
{
    int idx = blockIdx.x * 256 + threadIdx.x;    // 262144
    int d = idx & 63;
    int k = (idx >> 6) & 511;
    int h = idx >> 15;
    g_bw[((size_t)h*E_ + k) * 128 + 2*d    ] = __float2bfloat16(relw[(size_t)k*(2*E_) + h*64 + d]);
    g_bw[((size_t)h*E_ + k) * 128 + 2*d + 1] = __float2bfloat16(relw[(size_t)k*(2*E_) + E_ + h*64 + d]);
}

// ---------------- fused relation GEMM (bf16 HMMA, 3-stage, 2 CTAs/SM) ---------
#define RSA_STRIDE 16384
#define RSB_BASE   49152
#define RSB_STRIDE 16384
#define RELW_SMEM  98304
__global__ void __launch_bounds__(256, 2) relw_mma(const float* __restrict__ relb)
{
    extern __shared__ char smem[];
    const uint32_t AsBase = smem_u32(smem);
    const uint32_t BsBase = AsBase + RSB_BASE;
    float* red = (float*)smem;

    const int h   = blockIdx.x;
    const int n0  = blockIdx.y * 128;
    const int tid = threadIdx.x;
    const int lane = tid & 31, warp = tid >> 5;
    const int warp_m = warp >> 1, warp_n = warp & 1;

    float acc[2][8][4];
    #pragma unroll
    for (int i = 0; i < 2; i++)
        #pragma unroll
        for (int j = 0; j < 8; j++)
            #pragma unroll
            for (int k = 0; k < 4; k++) acc[i][j][k] = 0.f;

    const __nv_bfloat16* Ag = g_arel + (size_t)n0 * E_;
    const __nv_bfloat16* Bg = g_bw + (size_t)h * E_ * 128;

    auto load_stage = [&](int s, int buf) {
        uint32_t Ab = AsBase + buf * RSA_STRIDE;
        #pragma unroll
        for (int c = 0; c < 4; c++) {
            int idx = c * 256 + tid;
            int row = idx >> 3, cg = idx & 7;
            CP_ASYNC16(Ab + row*128 + (((cg ^ (row & 7)) << 4)),
                       Ag + (size_t)row * E_ + s*64 + cg*8);
        }
        uint32_t Bb = BsBase + buf * RSB_STRIDE;
        #pragma unroll
        for (int c = 0; c < 4; c++) {
            int idx = c * 256 + tid;
            int kr = idx >> 4, ng = idx & 15;
            CP_ASYNC16(Bb + kr*256 + (((ng ^ (kr & 7)) << 4)),
                       Bg + (size_t)(s*64 + kr) * 128 + ng*8);
        }
        CP_COMMIT();
    };

    load_stage(0, 0);
    load_stage(1, 1);

    const int a_r  = warp_m*32 + (lane & 15);
    const int a_kc = (lane >> 4) << 3;
    const int b_kr = lane & 15;
    const int b_nc = warp_n*64 + ((lane >> 4) << 3);

    #pragma unroll
    for (int s = 0; s < 8; s++) {
        if (s < 7) CP_WAIT1(); else CP_WAIT0();
        __syncthreads();
        if (s < 6) load_stage(s + 2, (s + 2) % 3);

        const uint32_t Ab = AsBase + (s % 3) * RSA_STRIDE;
        const uint32_t Bb = BsBase + (s % 3) * RSB_STRIDE;

        #pragma unroll
        for (int ks = 0; ks < 4; ks++) {
            uint32_t a[2][4];
            #pragma unroll
            for (int mi = 0; mi < 2; mi++) {
                int r  = a_r + mi*16;
                int kc = a_kc + ks*16;
                ldsm_x4(a[mi][0], a[mi][1], a[mi][2], a[mi][3],
                        Ab + r*128 + ((((kc >> 3) ^ (r & 7)) << 4)));
            }
            uint32_t b[8][2];
            #pragma unroll
            for (int g = 0; g < 4; g++) {
                int krow = b_kr + ks*16;
                int ncol = b_nc + g*16;
                ldsm_x4_t(b[2*g][0], b[2*g][1], b[2*g+1][0], b[2*g+1][1],
                          Bb + krow*256 + ((((ncol >> 3) ^ (krow & 7)) << 4)));
            }
            #pragma unroll
            for (int mi = 0; mi < 2; mi++)
                #pragma unroll
                for (int nf = 0; nf < 8; nf++)
                    mma16816(acc[mi][nf], a[mi], b[nf]);
        }
    }

    // ---- fused epilogue --------------------------------------------------------
    const int tig = lane & 3, grp = lane >> 2;
    float part[2][2] = {{0.f, 0.f}, {0.f, 0.f}};
    #pragma unroll
    for (int nf = 0; nf < 8; nf++) {
        int d = warp_n*32 + nf*4 + tig;
        float bra = relb[h*64 + d];
        float brb = relb[E_ + h*64 + d];
        #pragma unroll
        for (int mi = 0; mi < 2; mi++)
            #pragma unroll
            for (int hf = 0; hf < 2; hf++) {
                int r  = warp_m*32 + mi*16 + grp + hf*8;
                int n  = n0 + r;
                int b  = n & 31;
                int ji = n >> 5;
                int ii = ji & 63, jj = ji >> 6;
                float q = g_qkv[(size_t)(ii*B_ + b) * (3*E_) + h*64 + d];
                float k = g_qkv[(size_t)(jj*B_ + b) * (3*E_) + E_ + h*64 + d];
                part[mi][hf] += (acc[mi][nf][hf*2+0] + bra + q) * (acc[mi][nf][hf*2+1] + brb + k);
            }
    }
    #pragma unroll
    for (int mi = 0; mi < 2; mi++)
        #pragma unroll
        for (int hf = 0; hf < 2; hf++) {
            float v = part[mi][hf];
            v += __shfl_xor_sync(~0u, v, 1);
            v += __shfl_xor_sync(~0u, v, 2);
            part[mi][hf] = v;
        }
    __syncthreads();
    if (tig == 0) {
        #pragma unroll
        for (int mi = 0; mi < 2; mi++)
            #pragma unroll
            for (int hf = 0; hf < 2; hf++) {
                int r = warp_m*32 + mi*16 + grp + hf*8;
                red[r*2 + warp_n] = part[mi][hf];
            }
    }
    __syncthreads();
    if (tid < 128) {
        int n  = n0 + tid;
        int b  = n & 31;
        int ji = n >> 5;
        int ii = ji & 63, jj = ji >> 6;
        g_w[((size_t)(ii*B_ + b) * H_ + h) * T_ + jj] =
            (red[tid*2] + red[tid*2 + 1]) * 0.015625f;
    }
}

// ---------------- fp16 GEMM: (64*MI)x128 tile, K-stage 64, 3-stage ------------
// A [M,K] half row-major, B [K,N] half row-major.
// EPI 0: +bias, write float. EPI 1: relu, write half. EPI 2: +add fp32, write float.
template<int MI, int EPI>
__global__ void __launch_bounds__(256, 2) gemm_h16(
    const __half* __restrict__ A, const __half* __restrict__ Bm,
    const float* __restrict__ bias, const float* __restrict__ add,
    void* __restrict__ Cv, int M, int N, int K)
{
    constexpr int ASTRIDE = MI * 8192;   // 64*MI rows x 128B
    extern __shared__ char smem[];
    const uint32_t AsBase = smem_u32(smem);
    const uint32_t BsBase = AsBase + 3 * ASTRIDE;

    const int tid = threadIdx.x;
    const int lane = tid & 31, warp = tid >> 5;
    const int warp_m = warp >> 1, warp_n = warp & 1;
    const int m0 = blockIdx.y * (64 * MI);
    const int n0 = blockIdx.x * 128;

    float acc[MI][8][4];
    #pragma unroll
    for (int i = 0; i < MI; i++)
        #pragma unroll
        for (int j = 0; j < 8; j++)
            #pragma unroll
            for (int k = 0; k < 4; k++) acc[i][j][k] = 0.f;

    const __half* Ag = A + (size_t)m0 * K;
    const int S = K >> 6;

    auto load_stage = [&](int s, int buf) {
        uint32_t Ab = AsBase + buf * ASTRIDE;
        #pragma unroll
        for (int c = 0; c < 2*MI; c++) {
            int idx = c * 256 + tid;
            int row = idx >> 3, cg = idx & 7;
            CP_ASYNC16(Ab + row*128 + (((cg ^ (row & 7)) << 4)),
                       Ag + (size_t)row * K + s*64 + cg*8);
        }
        uint32_t Bb = BsBase + buf * RSB_STRIDE;
        #pragma unroll
        for (int c = 0; c < 4; c++) {
            int idx = c * 256 + tid;
            int kr = idx >> 4, ng = idx & 15;
            CP_ASYNC16(Bb + kr*256 + (((ng ^ (kr & 7)) << 4)),
                       Bm + (size_t)(s*64 + kr) * N + n0 + ng*8);
        }
        CP_COMMIT();
    };

    load_stage(0, 0);
    load_stage(1, 1);

    const int a_r  = warp_m*(16*MI) + (lane & 15);
    const int a_kc = (lane >> 4) << 3;
    const int b_kr = lane & 15;
    const int b_nc = warp_n*64 + ((lane >> 4) << 3);

    for (int s = 0; s < S; s++) {
        if (s < S - 1) CP_WAIT1(); else CP_WAIT0();
        __syncthreads();
        if (s < S - 2) load_stage(s + 2, (s + 2) % 3);

        const uint32_t Ab = AsBase + (s % 3) * ASTRIDE;
        const uint32_t Bb = BsBase + (s % 3) * RSB_STRIDE;

        #pragma unroll
        for (int ks = 0; ks < 4; ks++) {
            uint32_t a[MI][4];
            #pragma unroll
            for (int mi = 0; mi < MI; mi++) {
                int r  = a_r + mi*16;
                int kc = a_kc + ks*16;
                ldsm_x4(a[mi][0], a[mi][1], a[mi][2], a[mi][3],
                        Ab + r*128 + ((((kc >> 3) ^ (r & 7)) << 4)));
            }
            uint32_t b[8][2];
            #pragma unroll
            for (int g = 0; g < 4; g++) {
                int krow = b_kr + ks*16;
                int ncol = b_nc + g*16;
                ldsm_x4_t(b[2*g][0], b[2*g][1], b[2*g+1][0], b[2*g+1][1],
                          Bb + krow*256 + ((((ncol >> 3) ^ (krow & 7)) << 4)));
            }
            #pragma unroll
            for (int mi = 0; mi < MI; mi++)
                #pragma unroll
                for (int nf = 0; nf < 8; nf++)
                    mma16816h(acc[mi][nf], a[mi], b[nf]);
        }
    }

    // ---- epilogue ---------------------------------------------------------------
    const int tig = lane & 3, grp = lane >> 2;
    #pragma unroll
    for (int mi = 0; mi < MI; mi++)
        #pragma unroll
        for (int hf = 0; hf < 2; hf++) {
            int row = m0 + warp_m*(16*MI) + mi*16 + grp + hf*8;
            #pragma unroll
            for (int nf = 0; nf < 8; nf++) {
                int col = n0 + warp_n*64 + nf*8 + tig*2;
                float v0 = acc[mi][nf][hf*2 + 0] + bias[col];
                float v1 = acc[mi][nf][hf*2 + 1] + bias[col + 1];
                if (EPI == 1) {
                    v0 = fmaxf(v0, 0.f); v1 = fmaxf(v1, 0.f);
                    *(uint32_t*)((__half*)Cv + (size_t)row * N + col) = f2h2(v0, v1);
                } else {
                    if (EPI == 2) {
                        v0 += add[(size_t)row * N + col];
                        v1 += add[(size_t)row * N + col + 1];
                    }
                    *(float2*)((float*)Cv + (size_t)row * N + col) = make_float2(v0, v1);
                }
            }
        }
}

// ---------------- softmax + attn, one CTA per (b, h), fp16 output -------------
__global__ __launch_bounds__(256) void softmax_attn_kernel()
{
    const int b = blockIdx.x, h = blockIdx.y;
    __shared__ float p[64][68];
    __shared__ float vs[64][68];
    const int t = threadIdx.x;
    const int i = t >> 2, q = t & 3;
    const int d0 = q * 16;

    {
        const float* src = g_qkv + (size_t)(i*B_ + b)*(3*E_) + 2*E_ + h*64 + d0;
        #pragma unroll
        for (int e = 0; e < 16; e += 4)
            *(float4*)&vs[i][d0 + e] = *(const float4*)(src + e);
    }
    {
        float w[16];
        const float* wr = g_w + ((size_t)(i*B_ + b)*H_ + h)*T_ + d0;
        #pragma unroll
        for (int e = 0; e < 16; e += 4) {
            float4 v4 = *(const float4*)(wr + e);
            w[e] = v4.x; w[e+1] = v4.y; w[e+2] = v4.z; w[e+3] = v4.w;
        }
        float mx = w[0];
        #pragma unroll
        for (int e = 1; e < 16; e++) mx = fmaxf(mx, w[e]);
        mx = fmaxf(mx, __shfl_xor_sync(~0u, mx, 1));
        mx = fmaxf(mx, __shfl_xor_sync(~0u, mx, 2));
        float s = 0.f;
        #pragma unroll
        for (int e = 0; e < 16; e++) { w[e] = expf(w[e] - mx); s += w[e]; }
        s += __shfl_xor_sync(~0u, s, 1);
        s += __shfl_xor_sync(~0u, s, 2);
        float inv = 1.f / s;
        #pragma unroll
        for (int e = 0; e < 16; e++) p[i][d0 + e] = w[e] * inv;
    }
    __syncthreads();

    float acc[16] = {};
    for (int j = 0; j < 64; j++) {
        float pij = p[i][j];
        #pragma unroll
        for (int e = 0; e < 16; e += 4) {
            float4 v4 = *(float4*)&vs[j][d0 + e];
            acc[e]   = fmaf(pij, v4.x, acc[e]);
            acc[e+1] = fmaf(pij, v4.y, acc[e+1]);
            acc[e+2] = fmaf(pij, v4.z, acc[e+2]);
            acc[e+3] = fmaf(pij, v4.w, acc[e+3]);
        }
    }
    __half* dst = g_attnh + (size_t)(i*B_ + b)*E_ + h*64 + d0;
    #pragma unroll
    for (int e = 0; e < 16; e += 4)
        *(uint2*)(dst + e) = make_uint2(f2h2(acc[e], acc[e+1]), f2h2(acc[e+2], acc[e+3]));
}

// ---------------- layernorm (optional extra fp16 output) ----------------------
__global__ __launch_bounds__(256) void ln_kernel(
    const float* __restrict__ in, const float* __restrict__ g,
    const float* __restrict__ b, float* __restrict__ out,
    __half* __restrict__ hout)
{
    int row = blockIdx.x;
    const float* r = in + (size_t)row * E_;
    int t = threadIdx.x;
    float v0 = r[t], v1 = r[t + 256];
    float s = v0 + v1, sq = v0*v0 + v1*v1;
    #pragma unroll
    for (int o = 16; o; o >>= 1) {
        s  += __shfl_xor_sync(~0u, s,  o);
        sq += __shfl_xor_sync(~0u, sq, o);
    }
    __shared__ float ss[8], ssq[8];
    int w = t >> 5, l = t & 31;
    if (l == 0) { ss[w] = s; ssq[w] = sq; }
    __syncthreads();
    if (w == 0) {
        s  = (l < 8) ? ss[l]  : 0.f;
        sq = (l < 8) ? ssq[l] : 0.f;
        #pragma unroll
        for (int o = 4; o; o >>= 1) {
            s  += __shfl_xor_sync(~0u, s,  o);
            sq += __shfl_xor_sync(~0u, sq, o);
        }
        if (l == 0) { ss[0] = s; ssq[0] = sq; }
    }
    __syncthreads();
    float mu   = ss[0]  * (1.f / E_);
    float var  = ssq[0] * (1.f / E_) - mu * mu;
    float rstd = rsqrtf(var + 1e-5f);
    float o0 = (v0 - mu) * rstd * g[t]       + b[t];
    float o1 = (v1 - mu) * rstd * g[t + 256] + b[t + 256];
    out[(size_t)row*E_ + t]       = o0;
    out[(size_t)row*E_ + t + 256] = o1;
    if (hout) {
        hout[(size_t)row*E_ + t]       = __float2half_rn(o0);
        hout[(size_t)row*E_ + t + 256] = __float2half_rn(o1);
    }
}

// ---------------- launch --------------------------------------------------------
extern "C" void kernel_launch(void* const* d_in, const int* in_sizes, int n_in,
                              void* d_out, int out_size)
{
    const float* x        = (const float*)d_in[0];
    const float* relation = (const float*)d_in[1];
    const float* in_w     = (const float*)d_in[2];
    const float* in_b     = (const float*)d_in[3];
    const float* rel_w    = (const float*)d_in[4];
    const float* rel_b    = (const float*)d_in[5];
    const float* out_w    = (const float*)d_in[6];
    const float* out_b    = (const float*)d_in[7];
    const float* fc1_w    = (const float*)d_in[8];
    const float* fc1_b    = (const float*)d_in[9];
    const float* fc2_w    = (const float*)d_in[10];
    const float* fc2_b    = (const float*)d_in[11];
    const float* ln1_g    = (const float*)d_in[12];
    const float* ln1_b    = (const float*)d_in[13];
    const float* ln2_g    = (const float*)d_in[14];
    const float* ln2_b    = (const float*)d_in[15];
    float* out = (float*)d_out;

    const int SM_H2 = 3 * (16384 + 16384);   // MI=2: 98304
    const int SM_H1 = 3 * (8192  + 16384);   // MI=1: 73728

    static float *p_qkv = nullptr, *p_ao, *p_h, *p_f2;
    static __nv_bfloat16* p_arel;
    static __half *p_xh, *p_wqkT, *p_woh, *p_attnh, *p_hh, *p_f1h, *p_w1h, *p_w2h;
    static cudaStream_t s_side;
    static cudaEvent_t ev_fork, ev_join;
    if (!p_qkv) {
        cudaGetSymbolAddress((void**)&p_qkv,  g_qkv);
        cudaGetSymbolAddress((void**)&p_ao,   g_ao);
        cudaGetSymbolAddress((void**)&p_h,    g_h);
        cudaGetSymbolAddress((void**)&p_f2,   g_f2);
        cudaGetSymbolAddress((void**)&p_arel, g_arel);
        cudaGetSymbolAddress((void**)&p_xh,   g_xh);
        cudaGetSymbolAddress((void**)&p_wqkT, g_wqkT);
        cudaGetSymbolAddress((void**)&p_woh,  g_woh);
        cudaGetSymbolAddress((void**)&p_attnh,g_attnh);
        cudaGetSymbolAddress((void**)&p_hh,   g_hh);
        cudaGetSymbolAddress((void**)&p_f1h,  g_f1h);
        cudaGetSymbolAddress((void**)&p_w1h,  g_w1h);
        cudaGetSymbolAddress((void**)&p_w2h,  g_w2h);
        cudaFuncSetAttribute(relw_mma, cudaFuncAttributeMaxDynamicSharedMemorySize, RELW_SMEM);
        cudaFuncSetAttribute(gemm_h16<2, 0>, cudaFuncAttributeMaxDynamicSharedMemorySize, SM_H2);
        cudaFuncSetAttribute(gemm_h16<2, 1>, cudaFuncAttributeMaxDynamicSharedMemorySize, SM_H2);
        cudaFuncSetAttribute(gemm_h16<1, 2>, cudaFuncAttributeMaxDynamicSharedMemorySize, SM_H1);
        cudaStreamCreateWithFlags(&s_side, cudaStreamNonBlocking);
        cudaEventCreateWithFlags(&ev_fork, cudaEventDisableTiming);
        cudaEventCreateWithFlags(&ev_join, cudaEventDisableTiming);
    }

    dim3 blk(256);

    // ---- fork: cvt_rel on side stream (overlaps main prepasses + qkv) ----------
    cudaEventRecord(ev_fork, 0);
    cudaStreamWaitEvent(s_side, ev_fork, 0);
    cvt_rel<<<ROWS_ * E_ / (16 * 256), 256, 0, s_side>>>(relation, p_arel);
    cudaEventRecord(ev_join, s_side);

    // main: fp16 prepasses + qkv
    cvt_f16<<<TB_ * E_ / (8 * 256), 256>>>(x, p_xh);
    cvt_wT<<<(3*E_) * E_ / 256, 256>>>(in_w, p_wqkT, 3*E_, E_);
    cvt_f16<<<E_ * E_ / (8 * 256), 256>>>(out_w, p_woh);
    cvt_f16<<<E_ * F_ / (8 * 256), 256>>>(fc1_w, p_w1h);
    cvt_f16<<<F_ * E_ / (8 * 256), 256>>>(fc2_w, p_w2h);
    build_bw<<<1024, 256>>>(rel_w);

    // 1. qkv (fp16 HMMA, MI=2): grid 192
    gemm_h16<2, 0><<<dim3(1536/128, TB_/128), blk, SM_H2>>>(p_xh, p_wqkT, in_b, nullptr, p_qkv, TB_, 3*E_, E_);

    cudaStreamWaitEvent(0, ev_join, 0);

    // 2. relation GEMM (bf16 HMMA) + fused logits
    relw_mma<<<dim3(H_, ROWS_/128), blk, RELW_SMEM>>>(rel_b);

    // 3. softmax + attn (fp16 out), CTA per (b,h)
    softmax_attn_kernel<<<dim3(B_, H_), 256>>>();

    // 4. out proj + residual x  (fp16, MI=1: grid 128)
    gemm_h16<1, 2><<<dim3(E_/128, TB_/64), blk, SM_H1>>>(p_attnh, p_woh, out_b, x, p_ao, TB_, E_, E_);

    // 5. LN1 -> h (fp32) + h (fp16)
    ln_kernel<<<TB_, 256>>>(p_ao, ln1_g, ln1_b, p_h, p_hh);

    // 6. fc1 + relu  (fp16, MI=2: grid 256)
    gemm_h16<2, 1><<<dim3(F_/128, TB_/128), blk, SM_H2>>>(p_hh, p_w1h, fc1_b, nullptr, p_f1h, TB_, F_, E_);

    // 7. fc2 + residual h  (fp16, MI=1: grid 128)
    gemm_h16<1, 2><<<dim3(E_/128, TB_/64), blk, SM_H1>>>(p_f1h, p_w2h, fc2_b, p_h, p_f2, TB_, E_, F_);

    // 8. LN2 -> out
    ln_kernel<<<TB_, 256>>>(p_f2, ln2_g, ln2_b, out, nullptr);
}